// round 4
// baseline (speedup 1.0000x reference)
#include <cuda_runtime.h>
#include <cstdint>

#define N_NODES 500000
#define N_EDGES 2000000
#define C       32
#define NGRAPH  1024
#define HIDDEN  1024
#define LAYERS  8

#define SCAN_BLK 256
#define ITEMS    8
#define CHUNK    (SCAN_BLK * ITEMS)                       // 2048
#define NBLK     ((N_NODES + CHUNK - 1) / CHUNK)          // 245

// ---------------- device scratch (static; no runtime allocation) -------------
__device__ float d_xa  [(size_t)N_NODES * C];
__device__ float d_xb  [(size_t)N_NODES * C];
__device__ int   d_cnt [2][N_NODES];
__device__ int   d_off [2][N_NODES + 1];
__device__ int   d_cur [2][N_NODES];
__device__ int   d_csr [2][N_EDGES];
__device__ float d_norm[2][N_NODES];
__device__ int   d_bsum[2][NBLK];
__device__ float d_gsum[NGRAPH * C];
__device__ float d_gcnt[NGRAPH];

// ---------------- zero counters / pooling buffers ----------------------------
__global__ void k_zero()
{
    int i = blockIdx.x * blockDim.x + threadIdx.x;
    int stride = gridDim.x * blockDim.x;
    for (int j = i; j < N_NODES; j += stride) { d_cnt[0][j] = 0; d_cnt[1][j] = 0; }
    if (i < NGRAPH * C) d_gsum[i] = 0.f;
    if (i < NGRAPH)     d_gcnt[i] = 0.f;
}

// ---------------- degree histogram -------------------------------------------
__global__ void k_hist(const int* __restrict__ src, const int* __restrict__ dst, int E)
{
    int e = blockIdx.x * blockDim.x + threadIdx.x;
    if (e >= E) return;
    atomicAdd(&d_cnt[0][__ldg(dst + e)], 1);
    atomicAdd(&d_cnt[1][__ldg(src + e)], 1);
}

// ---------------- scan phase A: per-block sums --------------------------------
__global__ void k_scanA()
{
    int y = blockIdx.y;
    int base = blockIdx.x * CHUNK + threadIdx.x * ITEMS;
    int s = 0;
    #pragma unroll
    for (int j = 0; j < ITEMS; j++) {
        int i = base + j;
        if (i < N_NODES) s += d_cnt[y][i];
    }
    #pragma unroll
    for (int o = 16; o > 0; o >>= 1) s += __shfl_down_sync(0xffffffffu, s, o);
    __shared__ int sh[8];
    if ((threadIdx.x & 31) == 0) sh[threadIdx.x >> 5] = s;
    __syncthreads();
    if (threadIdx.x == 0) {
        int t = 0;
        #pragma unroll
        for (int w = 0; w < 8; w++) t += sh[w];
        d_bsum[y][blockIdx.x] = t;
    }
}

// ---------------- scan phase B: exclusive scan of block sums ------------------
__global__ void k_scanB(int E)
{
    int y = blockIdx.y;
    int tid = threadIdx.x;
    int lane = tid & 31, warp = tid >> 5;
    int val = (tid < NBLK) ? d_bsum[y][tid] : 0;
    int incl = val;
    #pragma unroll
    for (int o = 1; o < 32; o <<= 1) {
        int t = __shfl_up_sync(0xffffffffu, incl, o);
        if (lane >= o) incl += t;
    }
    __shared__ int shw[8];
    if (lane == 31) shw[warp] = incl;
    __syncthreads();
    if (warp == 0 && lane < 8) {
        int b = shw[lane], ib = b;
        #pragma unroll
        for (int o = 1; o < 8; o <<= 1) {
            int t = __shfl_up_sync(0xffu, ib, o);
            if (lane >= o) ib += t;
        }
        shw[lane] = ib - b;
    }
    __syncthreads();
    if (tid < NBLK) d_bsum[y][tid] = shw[warp] + incl - val;
    if (tid == 0) d_off[y][N_NODES] = E;
}

// ---------------- scan phase C: write offsets / cursors / norms ---------------
__global__ void k_scanC()
{
    int y = blockIdx.y;
    int lane = threadIdx.x & 31, warp = threadIdx.x >> 5;
    int base = blockIdx.x * CHUNK + threadIdx.x * ITEMS;

    int v[ITEMS]; int tsum = 0;
    #pragma unroll
    for (int j = 0; j < ITEMS; j++) {
        int i = base + j;
        v[j] = (i < N_NODES) ? d_cnt[y][i] : 0;
        tsum += v[j];
    }
    int incl = tsum;
    #pragma unroll
    for (int o = 1; o < 32; o <<= 1) {
        int t = __shfl_up_sync(0xffffffffu, incl, o);
        if (lane >= o) incl += t;
    }
    __shared__ int shw[8];
    if (lane == 31) shw[warp] = incl;
    __syncthreads();
    if (warp == 0 && lane < 8) {
        int b = shw[lane], ib = b;
        #pragma unroll
        for (int o = 1; o < 8; o <<= 1) {
            int t = __shfl_up_sync(0xffu, ib, o);
            if (lane >= o) ib += t;
        }
        shw[lane] = ib - b;
    }
    __syncthreads();
    int run = d_bsum[y][blockIdx.x] + shw[warp] + (incl - tsum);
    #pragma unroll
    for (int j = 0; j < ITEMS; j++) {
        int i = base + j;
        if (i < N_NODES) {
            d_off[y][i]  = run;
            d_cur[y][i]  = run;
            d_norm[y][i] = 1.f / (1.f + (float)v[j]);
            run += v[j];
        }
    }
}

// ---------------- CSR fill ----------------------------------------------------
__global__ void k_scatter(const int* __restrict__ src, const int* __restrict__ dst, int E)
{
    int e = blockIdx.x * blockDim.x + threadIdx.x;
    if (e >= E) return;
    int s = __ldg(src + e);
    int t = __ldg(dst + e);
    int p = atomicAdd(&d_cur[0][t], 1);  d_csr[0][p] = s;
    int q = atomicAdd(&d_cur[1][s], 1);  d_csr[1][q] = t;
}

// ---------------- init: x = emb[nodes] ----------------------------------------
__global__ void k_init_x(const int* __restrict__ nodes, const float* __restrict__ emb, int n)
{
    long long idx = (long long)blockIdx.x * blockDim.x + threadIdx.x;
    if (idx >= (long long)n * C) return;
    int node = (int)(idx >> 5);
    int c    = (int)(idx & 31);
    int t    = __ldg(nodes + node);
    d_xa[idx] = __ldg(emb + t * C + c);
}

// ---------------- fused layer: gather + norm + 2x GEMV + residual --------------
// Persistent grid-stride warps; warp per node; lane = channel.
// All neighbor indices (both directions combined) fetched with ONE coalesced
// load per node, rows gathered in unrolled batches of 8 independent LDGs.
__global__ void __launch_bounds__(256) k_layer(const float* __restrict__ xin,
                                               float* __restrict__ xout,
                                               const float* __restrict__ w, int n)
{
    __shared__ float sw[2 * C * C];              // 8 KB, loaded once per block
    for (int i = threadIdx.x; i < 2 * C * C; i += 256)
        sw[i] = __ldg(w + i);
    __syncthreads();

    const int lane   = threadIdx.x & 31;
    const int warp   = threadIdx.x >> 5;
    const int gwarp  = blockIdx.x * 8 + warp;
    const int nwarps = gridDim.x * 8;
    const unsigned FULL = 0xffffffffu;

    for (int node = gwarp; node < n; node += nwarps) {
        float xv = xin[(size_t)node * C + lane];

        int b0 = __ldg(&d_off[0][node]);
        int d0 = __ldg(&d_off[0][node + 1]) - b0;
        int b1 = __ldg(&d_off[1][node]);
        int d1 = __ldg(&d_off[1][node + 1]) - b1;
        int dt = d0 + d1;

        // lane-held combined neighbor index: entries [0,d0) = in-nbrs, [d0,dt) = out-nbrs
        int idx_l = 0;
        if (lane < d0)       idx_l = __ldg(&d_csr[0][b0 + lane]);
        else if (lane < dt)  idx_l = __ldg(&d_csr[1][b1 + lane - d0]);

        float hf = xv, hb = xv;
        int jm = (dt < 32) ? dt : 32;
        for (int j = 0; j < jm; j += 8) {
            float vs[8];
            #pragma unroll
            for (int k2 = 0; k2 < 8; k2++) {
                if (j + k2 < jm) {
                    int s = __shfl_sync(FULL, idx_l, j + k2);
                    vs[k2] = __ldg(xin + (size_t)s * C + lane);
                }
            }
            #pragma unroll
            for (int k2 = 0; k2 < 8; k2++) {
                if (j + k2 < jm) {
                    if (j + k2 < d0) hf += vs[k2]; else hb += vs[k2];
                }
            }
        }
        // rare tail: combined degree > 32
        for (int j = 32; j < dt; j++) {
            int s = (j < d0) ? __ldg(&d_csr[0][b0 + j]) : __ldg(&d_csr[1][b1 + j - d0]);
            float v = __ldg(xin + (size_t)s * C + lane);
            if (j < d0) hf += v; else hb += v;
        }

        hf *= __ldg(&d_norm[0][node]);
        hb *= __ldg(&d_norm[1][node]);

        // dual GEMV via shfl broadcast of h
        float a0 = 0.f, a1 = 0.f;
        #pragma unroll
        for (int k = 0; k < C; k++) {
            float hfk = __shfl_sync(FULL, hf, k);
            float hbk = __shfl_sync(FULL, hb, k);
            a0 = fmaf(hfk, sw[k * C + lane], a0);
            a1 = fmaf(hbk, sw[C * C + k * C + lane], a1);
        }
        xout[(size_t)node * C + lane] = xv + fmaxf(a0, 0.f) + fmaxf(a1, 0.f);
    }
}

// ---------------- pooling: per-graph sum + count (batch sorted) ----------------
__global__ void k_pool(const int* __restrict__ batch, const float* __restrict__ x, int n)
{
    int lane = threadIdx.x & 31;
    int warp = threadIdx.x >> 5;
    int base = blockIdx.x * 256 + warp * 32;

    float acc = 0.f;
    int cur = -1, run = 0;
    for (int j = 0; j < 32; j++) {
        int node = base + j;
        if (node >= n) break;
        int b = __ldg(batch + node);
        float v = __ldg(x + (size_t)node * C + lane);
        if (b != cur) {
            if (cur >= 0) {
                atomicAdd(&d_gsum[cur * C + lane], acc);
                if (lane == 0) atomicAdd(&d_gcnt[cur], (float)run);
            }
            cur = b; acc = 0.f; run = 0;
        }
        acc += v; run++;
    }
    if (cur >= 0) {
        atomicAdd(&d_gsum[cur * C + lane], acc);
        if (lane == 0) atomicAdd(&d_gcnt[cur], (float)run);
    }
}

// ---------------- MLP head: 8 graphs per block (reuse hidden_w columns) --------
#define GPB 8
__global__ void k_mlp(const float* __restrict__ hw, const float* __restrict__ hb,
                      const float* __restrict__ ow, float* __restrict__ out)
{
    __shared__ float gs[GPB][C];
    __shared__ float sout[GPB];
    int tid = threadIdx.x;
    if (tid < GPB * C) {
        int g = tid >> 5, c = tid & 31;
        int gb = blockIdx.x * GPB + g;
        gs[g][c] = d_gsum[gb * C + c] / d_gcnt[gb];
    }
    if (tid < GPB) sout[tid] = 0.f;
    __syncthreads();

    float part[GPB];
    #pragma unroll
    for (int g = 0; g < GPB; g++) part[g] = 0.f;

    for (int j = tid; j < HIDDEN; j += 256) {
        float h[GPB];
        float bj = __ldg(hb + j);
        #pragma unroll
        for (int g = 0; g < GPB; g++) h[g] = bj;
        #pragma unroll
        for (int k = 0; k < C; k++) {
            float wkj = __ldg(hw + k * HIDDEN + j);
            #pragma unroll
            for (int g = 0; g < GPB; g++)
                h[g] = fmaf(gs[g][k], wkj, h[g]);
        }
        float oj = __ldg(ow + j);
        #pragma unroll
        for (int g = 0; g < GPB; g++)
            part[g] += fmaxf(h[g], 0.f) * oj;
    }
    #pragma unroll
    for (int g = 0; g < GPB; g++) {
        float v = part[g];
        #pragma unroll
        for (int off = 16; off > 0; off >>= 1)
            v += __shfl_down_sync(0xffffffffu, v, off);
        if ((tid & 31) == 0) atomicAdd(&sout[g], v);
    }
    __syncthreads();
    if (tid < GPB) out[blockIdx.x * GPB + tid] = sout[tid];
}

// ---------------- launch ---------------------------------------------------------
extern "C" void kernel_launch(void* const* d_in, const int* in_sizes, int n_in,
                              void* d_out, int out_size)
{
    const int*   nodes    = (const int*)  d_in[0];
    const int*   sources  = (const int*)  d_in[1];
    const int*   targets  = (const int*)  d_in[2];
    const int*   batch    = (const int*)  d_in[3];
    const float* emb      = (const float*)d_in[4];
    const float* conv_w   = (const float*)d_in[5];
    const float* hidden_w = (const float*)d_in[6];
    const float* hidden_b = (const float*)d_in[7];
    const float* out_w    = (const float*)d_in[8];
    float*       out      = (float*)d_out;

    const int N = in_sizes[0];
    const int E = in_sizes[1];

    // CSR build
    k_zero   <<<(N_NODES + 255) / 256, 256>>>();
    k_hist   <<<(E + 255) / 256, 256>>>(sources, targets, E);
    k_scanA  <<<dim3(NBLK, 2), SCAN_BLK>>>();
    k_scanB  <<<dim3(1, 2),    SCAN_BLK>>>(E);
    k_scanC  <<<dim3(NBLK, 2), SCAN_BLK>>>();
    k_scatter<<<(E + 255) / 256, 256>>>(sources, targets, E);

    // init features
    {
        long long tot = (long long)N * C;
        k_init_x<<<(int)((tot + 255) / 256), 256>>>(nodes, emb, N);
    }

    // 8 fused layers, ping-pong (even count -> final in d_xa)
    const int nb = 148 * 8;          // persistent-ish grid
    float *xa = nullptr, *xb = nullptr;
    cudaGetSymbolAddress((void**)&xa, d_xa);
    cudaGetSymbolAddress((void**)&xb, d_xb);
    for (int l = 0; l < LAYERS; l++) {
        const float* wl = conv_w + (size_t)l * 2 * C * C;
        if ((l & 1) == 0) k_layer<<<nb, 256>>>(xa, xb, wl, N);
        else              k_layer<<<nb, 256>>>(xb, xa, wl, N);
    }
    k_pool<<<(N + 255) / 256, 256>>>(batch, xa, N);

    k_mlp<<<NGRAPH / GPB, 256>>>(hidden_w, hidden_b, out_w, out);
}

// round 5
// speedup vs baseline: 1.3149x; 1.3149x over previous
#include <cuda_runtime.h>
#include <cstdint>

#define N_NODES 500000
#define N_EDGES 2000000
#define C       32
#define NGRAPH  1024
#define HIDDEN  1024
#define LAYERS  8

#define SCAN_BLK 256
#define ITEMS    8
#define CHUNK    (SCAN_BLK * ITEMS)                       // 2048
#define NBLK     ((N_NODES + CHUNK - 1) / CHUNK)          // 245

// ---------------- device scratch (static; no runtime allocation) -------------
__device__ float d_xa  [(size_t)N_NODES * C];
__device__ float d_xb  [(size_t)N_NODES * C];
__device__ int   d_cnt [2][N_NODES];
__device__ int   d_off [2][N_NODES + 1];
__device__ int   d_cur [2][N_NODES];
__device__ int   d_csr [2][N_EDGES];
__device__ float d_norm[2][N_NODES];
__device__ int   d_bsum[2][NBLK];
__device__ float d_gsum[NGRAPH * C];
__device__ float d_gcnt[NGRAPH];

// ---------------- zero counters / pooling buffers ----------------------------
__global__ void k_zero()
{
    int i = blockIdx.x * blockDim.x + threadIdx.x;
    int stride = gridDim.x * blockDim.x;
    for (int j = i; j < N_NODES; j += stride) { d_cnt[0][j] = 0; d_cnt[1][j] = 0; }
    if (i < NGRAPH * C) d_gsum[i] = 0.f;
    if (i < NGRAPH)     d_gcnt[i] = 0.f;
}

// ---------------- degree histogram -------------------------------------------
__global__ void k_hist(const int* __restrict__ src, const int* __restrict__ dst, int E)
{
    int e = blockIdx.x * blockDim.x + threadIdx.x;
    if (e >= E) return;
    atomicAdd(&d_cnt[0][__ldg(dst + e)], 1);
    atomicAdd(&d_cnt[1][__ldg(src + e)], 1);
}

// ---------------- scan phase A: per-block sums --------------------------------
__global__ void k_scanA()
{
    int y = blockIdx.y;
    int base = blockIdx.x * CHUNK + threadIdx.x * ITEMS;
    int s = 0;
    #pragma unroll
    for (int j = 0; j < ITEMS; j++) {
        int i = base + j;
        if (i < N_NODES) s += d_cnt[y][i];
    }
    #pragma unroll
    for (int o = 16; o > 0; o >>= 1) s += __shfl_down_sync(0xffffffffu, s, o);
    __shared__ int sh[8];
    if ((threadIdx.x & 31) == 0) sh[threadIdx.x >> 5] = s;
    __syncthreads();
    if (threadIdx.x == 0) {
        int t = 0;
        #pragma unroll
        for (int w = 0; w < 8; w++) t += sh[w];
        d_bsum[y][blockIdx.x] = t;
    }
}

// ---------------- scan phase B: exclusive scan of block sums ------------------
__global__ void k_scanB(int E)
{
    int y = blockIdx.y;
    int tid = threadIdx.x;
    int lane = tid & 31, warp = tid >> 5;
    int val = (tid < NBLK) ? d_bsum[y][tid] : 0;
    int incl = val;
    #pragma unroll
    for (int o = 1; o < 32; o <<= 1) {
        int t = __shfl_up_sync(0xffffffffu, incl, o);
        if (lane >= o) incl += t;
    }
    __shared__ int shw[8];
    if (lane == 31) shw[warp] = incl;
    __syncthreads();
    if (warp == 0 && lane < 8) {
        int b = shw[lane], ib = b;
        #pragma unroll
        for (int o = 1; o < 8; o <<= 1) {
            int t = __shfl_up_sync(0xffu, ib, o);
            if (lane >= o) ib += t;
        }
        shw[lane] = ib - b;
    }
    __syncthreads();
    if (tid < NBLK) d_bsum[y][tid] = shw[warp] + incl - val;
    if (tid == 0) d_off[y][N_NODES] = E;
}

// ---------------- scan phase C: write offsets / cursors / norms ---------------
__global__ void k_scanC()
{
    int y = blockIdx.y;
    int lane = threadIdx.x & 31, warp = threadIdx.x >> 5;
    int base = blockIdx.x * CHUNK + threadIdx.x * ITEMS;

    int v[ITEMS]; int tsum = 0;
    #pragma unroll
    for (int j = 0; j < ITEMS; j++) {
        int i = base + j;
        v[j] = (i < N_NODES) ? d_cnt[y][i] : 0;
        tsum += v[j];
    }
    int incl = tsum;
    #pragma unroll
    for (int o = 1; o < 32; o <<= 1) {
        int t = __shfl_up_sync(0xffffffffu, incl, o);
        if (lane >= o) incl += t;
    }
    __shared__ int shw[8];
    if (lane == 31) shw[warp] = incl;
    __syncthreads();
    if (warp == 0 && lane < 8) {
        int b = shw[lane], ib = b;
        #pragma unroll
        for (int o = 1; o < 8; o <<= 1) {
            int t = __shfl_up_sync(0xffu, ib, o);
            if (lane >= o) ib += t;
        }
        shw[lane] = ib - b;
    }
    __syncthreads();
    int run = d_bsum[y][blockIdx.x] + shw[warp] + (incl - tsum);
    #pragma unroll
    for (int j = 0; j < ITEMS; j++) {
        int i = base + j;
        if (i < N_NODES) {
            d_off[y][i]  = run;
            d_cur[y][i]  = run;
            d_norm[y][i] = 1.f / (1.f + (float)v[j]);
            run += v[j];
        }
    }
}

// ---------------- CSR fill ----------------------------------------------------
__global__ void k_scatter(const int* __restrict__ src, const int* __restrict__ dst, int E)
{
    int e = blockIdx.x * blockDim.x + threadIdx.x;
    if (e >= E) return;
    int s = __ldg(src + e);
    int t = __ldg(dst + e);
    int p = atomicAdd(&d_cur[0][t], 1);  d_csr[0][p] = s;
    int q = atomicAdd(&d_cur[1][s], 1);  d_csr[1][q] = t;
}

// ---------------- init: x = emb[nodes] ----------------------------------------
__global__ void k_init_x(const int* __restrict__ nodes, const float* __restrict__ emb, int n)
{
    long long idx = (long long)blockIdx.x * blockDim.x + threadIdx.x;
    if (idx >= (long long)n * C) return;
    int node = (int)(idx >> 5);
    int c    = (int)(idx & 31);
    int t    = __ldg(nodes + node);
    d_xa[idx] = __ldg(emb + t * C + c);
}

// ---------------- fused layer: gather + norm + 2x GEMV + residual --------------
// warp handles 4 consecutive nodes; lane = channel. Both directions' gathers
// interleaved (8 independent loads in flight). Weights staged once per block.
#define NPW 4
__global__ void __launch_bounds__(256) k_layer(const float* __restrict__ xin,
                                               float* __restrict__ xout,
                                               const float* __restrict__ w, int n)
{
    __shared__ float sw[2 * C * C];              // 8 KB
    __shared__ float shf[8][C];
    __shared__ float shb[8][C];

    for (int i = threadIdx.x; i < 2 * C * C; i += 256)
        sw[i] = __ldg(w + i);
    __syncthreads();

    const int lane = threadIdx.x & 31;
    const int warp = threadIdx.x >> 5;
    const int base = (blockIdx.x * 8 + warp) * NPW;

    #pragma unroll 1
    for (int ni = 0; ni < NPW; ni++) {
        int node = base + ni;
        if (node >= n) break;

        float xv = xin[(size_t)node * C + lane];
        int b0 = __ldg(&d_off[0][node]);
        int e0 = __ldg(&d_off[0][node + 1]);
        int b1 = __ldg(&d_off[1][node]);
        int e1 = __ldg(&d_off[1][node + 1]);

        float hf = xv, hb = xv;
        int p0 = b0, p1 = b1;
        while (p0 < e0 || p1 < e1) {
            int n0 = e0 - p0; if (n0 > 4) n0 = 4;
            int n1 = e1 - p1; if (n1 > 4) n1 = 4;
            int s0[4], s1[4];
            #pragma unroll
            for (int k = 0; k < 4; k++) {
                if (k < n0) s0[k] = __ldg(&d_csr[0][p0 + k]);
                if (k < n1) s1[k] = __ldg(&d_csr[1][p1 + k]);
            }
            float v0[4], v1[4];
            #pragma unroll
            for (int k = 0; k < 4; k++) {
                if (k < n0) v0[k] = __ldg(xin + (size_t)s0[k] * C + lane);
                if (k < n1) v1[k] = __ldg(xin + (size_t)s1[k] * C + lane);
            }
            #pragma unroll
            for (int k = 0; k < 4; k++) {
                if (k < n0) hf += v0[k];
                if (k < n1) hb += v1[k];
            }
            p0 += n0; p1 += n1;
        }

        hf *= __ldg(&d_norm[0][node]);
        hb *= __ldg(&d_norm[1][node]);

        shf[warp][lane] = hf;
        shb[warp][lane] = hb;
        __syncwarp();

        float a0 = 0.f, a1 = 0.f;
        #pragma unroll
        for (int k = 0; k < C; k++) {
            a0 = fmaf(shf[warp][k], sw[k * C + lane], a0);
            a1 = fmaf(shb[warp][k], sw[C * C + k * C + lane], a1);
        }
        xout[(size_t)node * C + lane] = xv + fmaxf(a0, 0.f) + fmaxf(a1, 0.f);
        __syncwarp();
    }
}

// ---------------- pooling: per-graph sum + count (batch sorted) ----------------
__global__ void k_pool(const int* __restrict__ batch, const float* __restrict__ x, int n)
{
    int lane = threadIdx.x & 31;
    int warp = threadIdx.x >> 5;
    int base = blockIdx.x * 256 + warp * 32;

    float acc = 0.f;
    int cur = -1, run = 0;
    for (int j = 0; j < 32; j++) {
        int node = base + j;
        if (node >= n) break;
        int b = __ldg(batch + node);
        float v = __ldg(x + (size_t)node * C + lane);
        if (b != cur) {
            if (cur >= 0) {
                atomicAdd(&d_gsum[cur * C + lane], acc);
                if (lane == 0) atomicAdd(&d_gcnt[cur], (float)run);
            }
            cur = b; acc = 0.f; run = 0;
        }
        acc += v; run++;
    }
    if (cur >= 0) {
        atomicAdd(&d_gsum[cur * C + lane], acc);
        if (lane == 0) atomicAdd(&d_gcnt[cur], (float)run);
    }
}

// ---------------- MLP head: 8 graphs per block (reuse hidden_w columns) --------
#define GPB 8
__global__ void k_mlp(const float* __restrict__ hw, const float* __restrict__ hb,
                      const float* __restrict__ ow, float* __restrict__ out)
{
    __shared__ float gs[GPB][C];
    __shared__ float sout[GPB];
    int tid = threadIdx.x;
    if (tid < GPB * C) {
        int g = tid >> 5, c = tid & 31;
        int gb = blockIdx.x * GPB + g;
        gs[g][c] = d_gsum[gb * C + c] / d_gcnt[gb];
    }
    if (tid < GPB) sout[tid] = 0.f;
    __syncthreads();

    float part[GPB];
    #pragma unroll
    for (int g = 0; g < GPB; g++) part[g] = 0.f;

    for (int j = tid; j < HIDDEN; j += 256) {
        float h[GPB];
        float bj = __ldg(hb + j);
        #pragma unroll
        for (int g = 0; g < GPB; g++) h[g] = bj;
        #pragma unroll
        for (int k = 0; k < C; k++) {
            float wkj = __ldg(hw + k * HIDDEN + j);
            #pragma unroll
            for (int g = 0; g < GPB; g++)
                h[g] = fmaf(gs[g][k], wkj, h[g]);
        }
        float oj = __ldg(ow + j);
        #pragma unroll
        for (int g = 0; g < GPB; g++)
            part[g] += fmaxf(h[g], 0.f) * oj;
    }
    #pragma unroll
    for (int g = 0; g < GPB; g++) {
        float v = part[g];
        #pragma unroll
        for (int off = 16; off > 0; off >>= 1)
            v += __shfl_down_sync(0xffffffffu, v, off);
        if ((tid & 31) == 0) atomicAdd(&sout[g], v);
    }
    __syncthreads();
    if (tid < GPB) out[blockIdx.x * GPB + tid] = sout[tid];
}

// ---------------- launch ---------------------------------------------------------
extern "C" void kernel_launch(void* const* d_in, const int* in_sizes, int n_in,
                              void* d_out, int out_size)
{
    const int*   nodes    = (const int*)  d_in[0];
    const int*   sources  = (const int*)  d_in[1];
    const int*   targets  = (const int*)  d_in[2];
    const int*   batch    = (const int*)  d_in[3];
    const float* emb      = (const float*)d_in[4];
    const float* conv_w   = (const float*)d_in[5];
    const float* hidden_w = (const float*)d_in[6];
    const float* hidden_b = (const float*)d_in[7];
    const float* out_w    = (const float*)d_in[8];
    float*       out      = (float*)d_out;

    const int N = in_sizes[0];
    const int E = in_sizes[1];

    // CSR build
    k_zero   <<<(N_NODES + 255) / 256, 256>>>();
    k_hist   <<<(E + 255) / 256, 256>>>(sources, targets, E);
    k_scanA  <<<dim3(NBLK, 2), SCAN_BLK>>>();
    k_scanB  <<<dim3(1, 2),    SCAN_BLK>>>(E);
    k_scanC  <<<dim3(NBLK, 2), SCAN_BLK>>>();
    k_scatter<<<(E + 255) / 256, 256>>>(sources, targets, E);

    // init features
    {
        long long tot = (long long)N * C;
        k_init_x<<<(int)((tot + 255) / 256), 256>>>(nodes, emb, N);
    }

    // 8 fused layers, ping-pong (even count -> final in d_xa)
    const int nb = (N + 8 * NPW - 1) / (8 * NPW);     // 32 nodes per block
    float *xa = nullptr, *xb = nullptr;
    cudaGetSymbolAddress((void**)&xa, d_xa);
    cudaGetSymbolAddress((void**)&xb, d_xb);
    for (int l = 0; l < LAYERS; l++) {
        const float* wl = conv_w + (size_t)l * 2 * C * C;
        if ((l & 1) == 0) k_layer<<<nb, 256>>>(xa, xb, wl, N);
        else              k_layer<<<nb, 256>>>(xb, xa, wl, N);
    }
    k_pool<<<(N + 255) / 256, 256>>>(batch, xa, N);

    k_mlp<<<NGRAPH / GPB, 256>>>(hidden_w, hidden_b, out_w, out);
}

// round 6
// speedup vs baseline: 1.3496x; 1.0264x over previous
#include <cuda_runtime.h>
#include <cuda_fp16.h>
#include <cstdint>

#define N_NODES 500000
#define N_EDGES 2000000
#define C       32
#define NGRAPH  1024
#define HIDDEN  1024
#define LAYERS  8

#define SCAN_BLK 256
#define ITEMS    8
#define CHUNK    (SCAN_BLK * ITEMS)                       // 2048
#define NBLK     ((N_NODES + CHUNK - 1) / CHUNK)          // 245

// ---------------- device scratch (static; no runtime allocation) -------------
__device__ __half d_xh  [2][(size_t)N_NODES * C];         // fp16 feature ping/pong (2x32MB)
__device__ int    d_cnt [2][N_NODES];
__device__ int    d_off [2][N_NODES + 1];
__device__ int    d_cur [2][N_NODES];
__device__ int    d_csr [2][N_EDGES];
__device__ int4   d_meta[N_NODES];                        // {b0, d0, b1, d1}
__device__ int    d_bsum[2][NBLK];
__device__ float  d_gsum[NGRAPH * C];
__device__ float  d_gcnt[NGRAPH];

// ---------------- zero counters / pooling buffers ----------------------------
__global__ void k_zero()
{
    int i = blockIdx.x * blockDim.x + threadIdx.x;
    int stride = gridDim.x * blockDim.x;
    for (int j = i; j < N_NODES; j += stride) { d_cnt[0][j] = 0; d_cnt[1][j] = 0; }
    if (i < NGRAPH * C) d_gsum[i] = 0.f;
    if (i < NGRAPH)     d_gcnt[i] = 0.f;
}

// ---------------- degree histogram -------------------------------------------
__global__ void k_hist(const int* __restrict__ src, const int* __restrict__ dst, int E)
{
    int e = blockIdx.x * blockDim.x + threadIdx.x;
    if (e >= E) return;
    atomicAdd(&d_cnt[0][__ldg(dst + e)], 1);
    atomicAdd(&d_cnt[1][__ldg(src + e)], 1);
}

// ---------------- scan phase A: per-block sums --------------------------------
__global__ void k_scanA()
{
    int y = blockIdx.y;
    int base = blockIdx.x * CHUNK + threadIdx.x * ITEMS;
    int s = 0;
    #pragma unroll
    for (int j = 0; j < ITEMS; j++) {
        int i = base + j;
        if (i < N_NODES) s += d_cnt[y][i];
    }
    #pragma unroll
    for (int o = 16; o > 0; o >>= 1) s += __shfl_down_sync(0xffffffffu, s, o);
    __shared__ int sh[8];
    if ((threadIdx.x & 31) == 0) sh[threadIdx.x >> 5] = s;
    __syncthreads();
    if (threadIdx.x == 0) {
        int t = 0;
        #pragma unroll
        for (int w = 0; w < 8; w++) t += sh[w];
        d_bsum[y][blockIdx.x] = t;
    }
}

// ---------------- scan phase B: exclusive scan of block sums ------------------
__global__ void k_scanB(int E)
{
    int y = blockIdx.y;
    int tid = threadIdx.x;
    int lane = tid & 31, warp = tid >> 5;
    int val = (tid < NBLK) ? d_bsum[y][tid] : 0;
    int incl = val;
    #pragma unroll
    for (int o = 1; o < 32; o <<= 1) {
        int t = __shfl_up_sync(0xffffffffu, incl, o);
        if (lane >= o) incl += t;
    }
    __shared__ int shw[8];
    if (lane == 31) shw[warp] = incl;
    __syncthreads();
    if (warp == 0 && lane < 8) {
        int b = shw[lane], ib = b;
        #pragma unroll
        for (int o = 1; o < 8; o <<= 1) {
            int t = __shfl_up_sync(0xffu, ib, o);
            if (lane >= o) ib += t;
        }
        shw[lane] = ib - b;
    }
    __syncthreads();
    if (tid < NBLK) d_bsum[y][tid] = shw[warp] + incl - val;
    if (tid == 0) d_off[y][N_NODES] = E;
}

// ---------------- scan phase C: write offsets / cursors -----------------------
__global__ void k_scanC()
{
    int y = blockIdx.y;
    int lane = threadIdx.x & 31, warp = threadIdx.x >> 5;
    int base = blockIdx.x * CHUNK + threadIdx.x * ITEMS;

    int v[ITEMS]; int tsum = 0;
    #pragma unroll
    for (int j = 0; j < ITEMS; j++) {
        int i = base + j;
        v[j] = (i < N_NODES) ? d_cnt[y][i] : 0;
        tsum += v[j];
    }
    int incl = tsum;
    #pragma unroll
    for (int o = 1; o < 32; o <<= 1) {
        int t = __shfl_up_sync(0xffffffffu, incl, o);
        if (lane >= o) incl += t;
    }
    __shared__ int shw[8];
    if (lane == 31) shw[warp] = incl;
    __syncthreads();
    if (warp == 0 && lane < 8) {
        int b = shw[lane], ib = b;
        #pragma unroll
        for (int o = 1; o < 8; o <<= 1) {
            int t = __shfl_up_sync(0xffu, ib, o);
            if (lane >= o) ib += t;
        }
        shw[lane] = ib - b;
    }
    __syncthreads();
    int run = d_bsum[y][blockIdx.x] + shw[warp] + (incl - tsum);
    #pragma unroll
    for (int j = 0; j < ITEMS; j++) {
        int i = base + j;
        if (i < N_NODES) {
            d_off[y][i] = run;
            d_cur[y][i] = run;
            run += v[j];
        }
    }
}

// ---------------- meta pack: {b0,d0,b1,d1} per node ----------------------------
__global__ void k_meta(int n)
{
    int i = blockIdx.x * blockDim.x + threadIdx.x;
    if (i >= n) return;
    int b0 = d_off[0][i], e0 = d_off[0][i + 1];
    int b1 = d_off[1][i], e1 = d_off[1][i + 1];
    d_meta[i] = make_int4(b0, e0 - b0, b1, e1 - b1);
}

// ---------------- CSR fill ----------------------------------------------------
__global__ void k_scatter(const int* __restrict__ src, const int* __restrict__ dst, int E)
{
    int e = blockIdx.x * blockDim.x + threadIdx.x;
    if (e >= E) return;
    int s = __ldg(src + e);
    int t = __ldg(dst + e);
    int p = atomicAdd(&d_cur[0][t], 1);  d_csr[0][p] = s;
    int q = atomicAdd(&d_cur[1][s], 1);  d_csr[1][q] = t;
}

// ---------------- init: x = emb[nodes] (fp16) ----------------------------------
__global__ void k_init_x(const int* __restrict__ nodes, const float* __restrict__ emb, int n)
{
    long long idx = (long long)blockIdx.x * blockDim.x + threadIdx.x;
    if (idx >= (long long)n * C) return;
    int node = (int)(idx >> 5);
    int c    = (int)(idx & 31);
    int t    = __ldg(nodes + node);
    d_xh[0][idx] = __float2half_rn(__ldg(emb + t * C + c));
}

// ---------------- fused layer (fp16 storage, fp32 compute) ---------------------
// warp handles 4 nodes; lane = channel. Dual-direction interleaved gathers.
#define NPW 4
__global__ void __launch_bounds__(256) k_layer(const __half* __restrict__ xin,
                                               __half* __restrict__ xout,
                                               const float* __restrict__ w, int n)
{
    __shared__ float sw[2 * C * C];              // 8 KB weights
    __shared__ float shf[8][C];
    __shared__ float shb[8][C];

    for (int i = threadIdx.x; i < 2 * C * C; i += 256)
        sw[i] = __ldg(w + i);
    __syncthreads();

    const int lane = threadIdx.x & 31;
    const int warp = threadIdx.x >> 5;
    const int base = (blockIdx.x * 8 + warp) * NPW;

    #pragma unroll 1
    for (int ni = 0; ni < NPW; ni++) {
        int node = base + ni;
        if (node >= n) break;

        int4 m = __ldg(&d_meta[node]);            // b0,d0,b1,d1 (uniform, 1 sector)
        float xv = __half2float(__ldg(xin + (size_t)node * C + lane));

        float hf = xv, hb = xv;
        int p0 = m.x, e0 = m.x + m.y;
        int p1 = m.z, e1 = m.z + m.w;
        while (p0 < e0 || p1 < e1) {
            int n0 = e0 - p0; if (n0 > 4) n0 = 4;
            int n1 = e1 - p1; if (n1 > 4) n1 = 4;
            int s0[4], s1[4];
            #pragma unroll
            for (int k = 0; k < 4; k++) {
                if (k < n0) s0[k] = __ldg(&d_csr[0][p0 + k]);
                if (k < n1) s1[k] = __ldg(&d_csr[1][p1 + k]);
            }
            __half v0[4], v1[4];
            #pragma unroll
            for (int k = 0; k < 4; k++) {
                if (k < n0) v0[k] = __ldg(xin + (size_t)s0[k] * C + lane);
                if (k < n1) v1[k] = __ldg(xin + (size_t)s1[k] * C + lane);
            }
            #pragma unroll
            for (int k = 0; k < 4; k++) {
                if (k < n0) hf += __half2float(v0[k]);
                if (k < n1) hb += __half2float(v1[k]);
            }
            p0 += n0; p1 += n1;
        }

        hf *= __fdividef(1.f, 1.f + (float)m.y);
        hb *= __fdividef(1.f, 1.f + (float)m.w);

        shf[warp][lane] = hf;
        shb[warp][lane] = hb;
        __syncwarp();

        float a0 = 0.f, a1 = 0.f;
        #pragma unroll
        for (int k = 0; k < C; k++) {
            a0 = fmaf(shf[warp][k], sw[k * C + lane], a0);
            a1 = fmaf(shb[warp][k], sw[C * C + k * C + lane], a1);
        }
        xout[(size_t)node * C + lane] =
            __float2half_rn(xv + fmaxf(a0, 0.f) + fmaxf(a1, 0.f));
        __syncwarp();
    }
}

// ---------------- pooling: per-graph sum + count (batch sorted) ----------------
__global__ void k_pool(const int* __restrict__ batch, const __half* __restrict__ x, int n)
{
    int lane = threadIdx.x & 31;
    int warp = threadIdx.x >> 5;
    int base = blockIdx.x * 256 + warp * 32;

    float acc = 0.f;
    int cur = -1, run = 0;
    for (int j = 0; j < 32; j++) {
        int node = base + j;
        if (node >= n) break;
        int b = __ldg(batch + node);
        float v = __half2float(__ldg(x + (size_t)node * C + lane));
        if (b != cur) {
            if (cur >= 0) {
                atomicAdd(&d_gsum[cur * C + lane], acc);
                if (lane == 0) atomicAdd(&d_gcnt[cur], (float)run);
            }
            cur = b; acc = 0.f; run = 0;
        }
        acc += v; run++;
    }
    if (cur >= 0) {
        atomicAdd(&d_gsum[cur * C + lane], acc);
        if (lane == 0) atomicAdd(&d_gcnt[cur], (float)run);
    }
}

// ---------------- MLP head: 8 graphs per block ---------------------------------
#define GPB 8
__global__ void k_mlp(const float* __restrict__ hw, const float* __restrict__ hb,
                      const float* __restrict__ ow, float* __restrict__ out)
{
    __shared__ float gs[GPB][C];
    __shared__ float sout[GPB];
    int tid = threadIdx.x;
    if (tid < GPB * C) {
        int g = tid >> 5, c = tid & 31;
        int gb = blockIdx.x * GPB + g;
        gs[g][c] = d_gsum[gb * C + c] / d_gcnt[gb];
    }
    if (tid < GPB) sout[tid] = 0.f;
    __syncthreads();

    float part[GPB];
    #pragma unroll
    for (int g = 0; g < GPB; g++) part[g] = 0.f;

    for (int j = tid; j < HIDDEN; j += 256) {
        float h[GPB];
        float bj = __ldg(hb + j);
        #pragma unroll
        for (int g = 0; g < GPB; g++) h[g] = bj;
        #pragma unroll
        for (int k = 0; k < C; k++) {
            float wkj = __ldg(hw + k * HIDDEN + j);
            #pragma unroll
            for (int g = 0; g < GPB; g++)
                h[g] = fmaf(gs[g][k], wkj, h[g]);
        }
        float oj = __ldg(ow + j);
        #pragma unroll
        for (int g = 0; g < GPB; g++)
            part[g] += fmaxf(h[g], 0.f) * oj;
    }
    #pragma unroll
    for (int g = 0; g < GPB; g++) {
        float v = part[g];
        #pragma unroll
        for (int off = 16; off > 0; off >>= 1)
            v += __shfl_down_sync(0xffffffffu, v, off);
        if ((tid & 31) == 0) atomicAdd(&sout[g], v);
    }
    __syncthreads();
    if (tid < GPB) out[blockIdx.x * GPB + tid] = sout[tid];
}

// ---------------- launch ---------------------------------------------------------
extern "C" void kernel_launch(void* const* d_in, const int* in_sizes, int n_in,
                              void* d_out, int out_size)
{
    const int*   nodes    = (const int*)  d_in[0];
    const int*   sources  = (const int*)  d_in[1];
    const int*   targets  = (const int*)  d_in[2];
    const int*   batch    = (const int*)  d_in[3];
    const float* emb      = (const float*)d_in[4];
    const float* conv_w   = (const float*)d_in[5];
    const float* hidden_w = (const float*)d_in[6];
    const float* hidden_b = (const float*)d_in[7];
    const float* out_w    = (const float*)d_in[8];
    float*       out      = (float*)d_out;

    const int N = in_sizes[0];
    const int E = in_sizes[1];

    // CSR build
    k_zero   <<<(N_NODES + 255) / 256, 256>>>();
    k_hist   <<<(E + 255) / 256, 256>>>(sources, targets, E);
    k_scanA  <<<dim3(NBLK, 2), SCAN_BLK>>>();
    k_scanB  <<<dim3(1, 2),    SCAN_BLK>>>(E);
    k_scanC  <<<dim3(NBLK, 2), SCAN_BLK>>>();
    k_meta   <<<(N + 255) / 256, 256>>>(N);
    k_scatter<<<(E + 255) / 256, 256>>>(sources, targets, E);

    // init features (fp16)
    {
        long long tot = (long long)N * C;
        k_init_x<<<(int)((tot + 255) / 256), 256>>>(nodes, emb, N);
    }

    // 8 fused layers, ping-pong (even count -> final in buffer 0)
    const int nb = (N + 8 * NPW - 1) / (8 * NPW);
    __half *xh = nullptr;
    cudaGetSymbolAddress((void**)&xh, d_xh);
    __half* xa = xh;
    __half* xb = xh + (size_t)N_NODES * C;
    for (int l = 0; l < LAYERS; l++) {
        const float* wl = conv_w + (size_t)l * 2 * C * C;
        if ((l & 1) == 0) k_layer<<<nb, 256>>>(xa, xb, wl, N);
        else              k_layer<<<nb, 256>>>(xb, xa, wl, N);
    }
    k_pool<<<(N + 255) / 256, 256>>>(batch, xa, N);

    k_mlp<<<NGRAPH / GPB, 256>>>(hidden_w, hidden_b, out_w, out);
}

// round 7
// speedup vs baseline: 1.3871x; 1.0278x over previous
#include <cuda_runtime.h>
#include <cuda_fp16.h>
#include <cstdint>

#define N_NODES 500000
#define N_EDGES 2000000
#define C       32
#define NGRAPH  1024
#define HIDDEN  1024
#define LAYERS  8

#define SCAN_BLK 256
#define ITEMS    8
#define CHUNK    (SCAN_BLK * ITEMS)                       // 2048
#define NBLK     ((N_NODES + CHUNK - 1) / CHUNK)          // 245

// ---------------- device scratch (static; zero-initialized at load) ----------
__device__ __half d_xh  [2][(size_t)N_NODES * C];         // fp16 feature ping/pong
__device__ int    d_cnt [2][N_NODES];                     // degrees (self-cleaned by scanC)
__device__ int    d_cur [2][N_NODES];                     // scatter cursors
__device__ int    d_csr [2][N_EDGES];
__device__ int4   d_meta[N_NODES];                        // {b0, d0, b1, d1}
__device__ int    d_bsum[2][NBLK];
__device__ float  d_gsum[NGRAPH * C];                     // self-cleaned by k_mlp
__device__ float  d_gcnt[NGRAPH];

// ---------------- degree histogram (d_cnt zeroed by previous scanC) -----------
__global__ void k_hist(const int* __restrict__ src, const int* __restrict__ dst, int E)
{
    int e = blockIdx.x * blockDim.x + threadIdx.x;
    if (e >= E) return;
    atomicAdd(&d_cnt[0][__ldg(dst + e)], 1);
    atomicAdd(&d_cnt[1][__ldg(src + e)], 1);
}

// ---------------- scan phase A: per-block sums --------------------------------
__global__ void k_scanA()
{
    int y = blockIdx.y;
    int base = blockIdx.x * CHUNK + threadIdx.x * ITEMS;
    int s = 0;
    #pragma unroll
    for (int j = 0; j < ITEMS; j++) {
        int i = base + j;
        if (i < N_NODES) s += d_cnt[y][i];
    }
    #pragma unroll
    for (int o = 16; o > 0; o >>= 1) s += __shfl_down_sync(0xffffffffu, s, o);
    __shared__ int sh[8];
    if ((threadIdx.x & 31) == 0) sh[threadIdx.x >> 5] = s;
    __syncthreads();
    if (threadIdx.x == 0) {
        int t = 0;
        #pragma unroll
        for (int w = 0; w < 8; w++) t += sh[w];
        d_bsum[y][blockIdx.x] = t;
    }
}

// ---------------- scan phase B: exclusive scan of block sums ------------------
__global__ void k_scanB()
{
    int y = blockIdx.y;
    int tid = threadIdx.x;
    int lane = tid & 31, warp = tid >> 5;
    int val = (tid < NBLK) ? d_bsum[y][tid] : 0;
    int incl = val;
    #pragma unroll
    for (int o = 1; o < 32; o <<= 1) {
        int t = __shfl_up_sync(0xffffffffu, incl, o);
        if (lane >= o) incl += t;
    }
    __shared__ int shw[8];
    if (lane == 31) shw[warp] = incl;
    __syncthreads();
    if (warp == 0 && lane < 8) {
        int b = shw[lane], ib = b;
        #pragma unroll
        for (int o = 1; o < 8; o <<= 1) {
            int t = __shfl_up_sync(0xffu, ib, o);
            if (lane >= o) ib += t;
        }
        shw[lane] = ib - b;
    }
    __syncthreads();
    if (tid < NBLK) d_bsum[y][tid] = shw[warp] + incl - val;
}

// ---------------- scan phase C: meta/cursors; re-zero counters ----------------
__global__ void k_scanC()
{
    int y = blockIdx.y;
    int lane = threadIdx.x & 31, warp = threadIdx.x >> 5;
    int base = blockIdx.x * CHUNK + threadIdx.x * ITEMS;

    int v[ITEMS]; int tsum = 0;
    #pragma unroll
    for (int j = 0; j < ITEMS; j++) {
        int i = base + j;
        v[j] = (i < N_NODES) ? d_cnt[y][i] : 0;
        tsum += v[j];
    }
    int incl = tsum;
    #pragma unroll
    for (int o = 1; o < 32; o <<= 1) {
        int t = __shfl_up_sync(0xffffffffu, incl, o);
        if (lane >= o) incl += t;
    }
    __shared__ int shw[8];
    if (lane == 31) shw[warp] = incl;
    __syncthreads();
    if (warp == 0 && lane < 8) {
        int b = shw[lane], ib = b;
        #pragma unroll
        for (int o = 1; o < 8; o <<= 1) {
            int t = __shfl_up_sync(0xffu, ib, o);
            if (lane >= o) ib += t;
        }
        shw[lane] = ib - b;
    }
    __syncthreads();
    int run = d_bsum[y][blockIdx.x] + shw[warp] + (incl - tsum);
    #pragma unroll
    for (int j = 0; j < ITEMS; j++) {
        int i = base + j;
        if (i < N_NODES) {
            int* mp = (int*)&d_meta[i];
            mp[y * 2 + 0] = run;          // base
            mp[y * 2 + 1] = v[j];         // degree
            d_cur[y][i]   = run;
            d_cnt[y][i]   = 0;            // self-clean for next call
            run += v[j];
        }
    }
}

// ---------------- fused CSR fill + feature init --------------------------------
__global__ void k_scatter_init(const int* __restrict__ src, const int* __restrict__ dst,
                               const int* __restrict__ nodes, const float* __restrict__ emb,
                               int E, int n)
{
    int idx = blockIdx.x * blockDim.x + threadIdx.x;
    if (idx < n * C) {
        int node = idx >> 5;
        int c    = idx & 31;
        int t    = __ldg(nodes + node);
        d_xh[0][idx] = __float2half_rn(__ldg(emb + t * C + c));
    }
    if (idx < E) {
        int s = __ldg(src + idx);
        int t = __ldg(dst + idx);
        int p = atomicAdd(&d_cur[0][t], 1);  d_csr[0][p] = s;
        int q = atomicAdd(&d_cur[1][s], 1);  d_csr[1][q] = t;
    }
}

// ---------------- mma.m16n8k16 helper -------------------------------------------
__device__ __forceinline__ void mma_16816(float* d,
                                          uint32_t a0, uint32_t a1, uint32_t a2, uint32_t a3,
                                          uint32_t b0, uint32_t b1)
{
    asm volatile(
        "mma.sync.aligned.m16n8k16.row.col.f32.f16.f16.f32 "
        "{%0,%1,%2,%3}, {%4,%5,%6,%7}, {%8,%9}, {%0,%1,%2,%3};"
        : "+f"(d[0]), "+f"(d[1]), "+f"(d[2]), "+f"(d[3])
        : "r"(a0), "r"(a1), "r"(a2), "r"(a3), "r"(b0), "r"(b1));
}

// ---------------- fused layer: gather + norm -> tensor-core GEMM -> residual ---
// 512 threads = 16 warps; 64 nodes per block. Gather: warp per node (4 serial),
// lane = channel. Conv: H[64x32] @ W[32x32] per direction via mma (fp16 in, fp32 acc).
#define NPW 4
__global__ void __launch_bounds__(512) k_layer(const __half* __restrict__ xin,
                                               __half* __restrict__ xout,
                                               const float* __restrict__ w, int n)
{
    __shared__ __half s_wt[2][32][32];   // transposed weights: s_wt[d][j][k] = w[d][k][j]
    __shared__ __half s_h [2][64][32];   // aggregated+normalized features per direction
    __shared__ __half s_x [64][32];      // residual
    __shared__ float  s_a [2][64][32];   // per-direction relu(GEMM) results

    // stage transposed fp16 weights (once per block)
    for (int i = threadIdx.x; i < 2 * 32 * 32; i += 512) {
        int d = i >> 10, rem = i & 1023, k = rem >> 5, j = rem & 31;
        s_wt[d][j][k] = __float2half_rn(__ldg(w + d * 1024 + k * 32 + j));
    }

    const int lane = threadIdx.x & 31;
    const int warp = threadIdx.x >> 5;
    const int blockBase = blockIdx.x * 64;

    // ---- gather phase: warp handles 4 nodes serially ----
    #pragma unroll 1
    for (int ni = 0; ni < NPW; ni++) {
        int nl   = warp * NPW + ni;
        int node = blockBase + nl;
        if (node < n) {
            int4 m = __ldg(&d_meta[node]);
            float xvf;
            __half xv = __ldg(xin + (size_t)node * C + lane);
            xvf = __half2float(xv);

            float hf = xvf, hb = xvf;
            int p0 = m.x, e0 = m.x + m.y;
            int p1 = m.z, e1 = m.z + m.w;
            while (p0 < e0 || p1 < e1) {
                int n0 = e0 - p0; if (n0 > 4) n0 = 4;
                int n1 = e1 - p1; if (n1 > 4) n1 = 4;
                int s0[4], s1[4];
                #pragma unroll
                for (int k = 0; k < 4; k++) {
                    if (k < n0) s0[k] = __ldg(&d_csr[0][p0 + k]);
                    if (k < n1) s1[k] = __ldg(&d_csr[1][p1 + k]);
                }
                __half v0[4], v1[4];
                #pragma unroll
                for (int k = 0; k < 4; k++) {
                    if (k < n0) v0[k] = __ldg(xin + (size_t)s0[k] * C + lane);
                    if (k < n1) v1[k] = __ldg(xin + (size_t)s1[k] * C + lane);
                }
                #pragma unroll
                for (int k = 0; k < 4; k++) {
                    if (k < n0) hf += __half2float(v0[k]);
                    if (k < n1) hb += __half2float(v1[k]);
                }
                p0 += n0; p1 += n1;
            }
            hf *= __fdividef(1.f, 1.f + (float)m.y);
            hb *= __fdividef(1.f, 1.f + (float)m.w);

            s_h[0][nl][lane] = __float2half_rn(hf);
            s_h[1][nl][lane] = __float2half_rn(hb);
            s_x[nl][lane]    = xv;
        } else {
            s_h[0][nl][lane] = __ushort_as_half((unsigned short)0);
            s_h[1][nl][lane] = __ushort_as_half((unsigned short)0);
            s_x[nl][lane]    = __ushort_as_half((unsigned short)0);
        }
    }
    __syncthreads();

    // ---- GEMM phase: warp -> (dir, m-tile, 2 n-tiles) ----
    {
        const int dir = warp >> 3;
        const int wm  = (warp & 7) >> 1;      // m-tile 0..3 (16 rows each)
        const int wn  = (warp & 1) * 2;       // first of 2 n-tiles (8 cols each)
        const int g   = lane >> 2;
        const int t   = lane & 3;
        const int m0  = wm * 16;

        float acc0[4] = {0.f, 0.f, 0.f, 0.f};
        float acc1[4] = {0.f, 0.f, 0.f, 0.f};

        #pragma unroll
        for (int kt = 0; kt < 32; kt += 16) {
            uint32_t a0 = *(const uint32_t*)&s_h[dir][m0 + g    ][kt + t * 2];
            uint32_t a1 = *(const uint32_t*)&s_h[dir][m0 + g + 8][kt + t * 2];
            uint32_t a2 = *(const uint32_t*)&s_h[dir][m0 + g    ][kt + t * 2 + 8];
            uint32_t a3 = *(const uint32_t*)&s_h[dir][m0 + g + 8][kt + t * 2 + 8];

            int n0 = wn * 8;
            uint32_t b0 = *(const uint32_t*)&s_wt[dir][n0 + g][kt + t * 2];
            uint32_t b1 = *(const uint32_t*)&s_wt[dir][n0 + g][kt + t * 2 + 8];
            mma_16816(acc0, a0, a1, a2, a3, b0, b1);

            int n1 = (wn + 1) * 8;
            uint32_t c0 = *(const uint32_t*)&s_wt[dir][n1 + g][kt + t * 2];
            uint32_t c1 = *(const uint32_t*)&s_wt[dir][n1 + g][kt + t * 2 + 8];
            mma_16816(acc1, a0, a1, a2, a3, c0, c1);
        }

        int n0 = wn * 8, n1 = (wn + 1) * 8;
        *(float2*)&s_a[dir][m0 + g    ][n0 + t * 2] =
            make_float2(fmaxf(acc0[0], 0.f), fmaxf(acc0[1], 0.f));
        *(float2*)&s_a[dir][m0 + g + 8][n0 + t * 2] =
            make_float2(fmaxf(acc0[2], 0.f), fmaxf(acc0[3], 0.f));
        *(float2*)&s_a[dir][m0 + g    ][n1 + t * 2] =
            make_float2(fmaxf(acc1[0], 0.f), fmaxf(acc1[1], 0.f));
        *(float2*)&s_a[dir][m0 + g + 8][n1 + t * 2] =
            make_float2(fmaxf(acc1[2], 0.f), fmaxf(acc1[3], 0.f));
    }
    __syncthreads();

    // ---- epilogue: out = x + relu(A0) + relu(A1), half2 stores ----
    for (int i = threadIdx.x; i < 64 * 32 / 2; i += 512) {
        int nl = i >> 4;
        int c2 = (i & 15) * 2;
        int node = blockBase + nl;
        if (node < n) {
            float r0 = __half2float(s_x[nl][c2])     + s_a[0][nl][c2]     + s_a[1][nl][c2];
            float r1 = __half2float(s_x[nl][c2 + 1]) + s_a[0][nl][c2 + 1] + s_a[1][nl][c2 + 1];
            *(__half2*)&xout[(size_t)node * C + c2] = __floats2half2_rn(r0, r1);
        }
    }
}

// ---------------- pooling: per-graph sum + count (batch sorted) ----------------
__global__ void k_pool(const int* __restrict__ batch, const __half* __restrict__ x, int n)
{
    int lane = threadIdx.x & 31;
    int warp = threadIdx.x >> 5;
    int base = blockIdx.x * 256 + warp * 32;

    float acc = 0.f;
    int cur = -1, run = 0;
    for (int j = 0; j < 32; j++) {
        int node = base + j;
        if (node >= n) break;
        int b = __ldg(batch + node);
        float v = __half2float(__ldg(x + (size_t)node * C + lane));
        if (b != cur) {
            if (cur >= 0) {
                atomicAdd(&d_gsum[cur * C + lane], acc);
                if (lane == 0) atomicAdd(&d_gcnt[cur], (float)run);
            }
            cur = b; acc = 0.f; run = 0;
        }
        acc += v; run++;
    }
    if (cur >= 0) {
        atomicAdd(&d_gsum[cur * C + lane], acc);
        if (lane == 0) atomicAdd(&d_gcnt[cur], (float)run);
    }
}

// ---------------- MLP head: 8 graphs per block; self-cleans pool buffers -------
#define GPB 8
__global__ void k_mlp(const float* __restrict__ hw, const float* __restrict__ hb,
                      const float* __restrict__ ow, float* __restrict__ out)
{
    __shared__ float gs[GPB][C];
    __shared__ float sout[GPB];
    int tid = threadIdx.x;
    if (tid < GPB * C) {
        int g = tid >> 5, c = tid & 31;
        int gb = blockIdx.x * GPB + g;
        gs[g][c] = d_gsum[gb * C + c] / d_gcnt[gb];
    }
    if (tid < GPB) sout[tid] = 0.f;
    __syncthreads();
    // self-clean for next kernel_launch call (all reads done)
    if (tid < GPB * C) {
        int g = tid >> 5, c = tid & 31;
        d_gsum[(blockIdx.x * GPB + g) * C + c] = 0.f;
    }
    if (tid < GPB) d_gcnt[blockIdx.x * GPB + tid] = 0.f;

    float part[GPB];
    #pragma unroll
    for (int g = 0; g < GPB; g++) part[g] = 0.f;

    for (int j = tid; j < HIDDEN; j += 256) {
        float h[GPB];
        float bj = __ldg(hb + j);
        #pragma unroll
        for (int g = 0; g < GPB; g++) h[g] = bj;
        #pragma unroll
        for (int k = 0; k < C; k++) {
            float wkj = __ldg(hw + k * HIDDEN + j);
            #pragma unroll
            for (int g = 0; g < GPB; g++)
                h[g] = fmaf(gs[g][k], wkj, h[g]);
        }
        float oj = __ldg(ow + j);
        #pragma unroll
        for (int g = 0; g < GPB; g++)
            part[g] += fmaxf(h[g], 0.f) * oj;
    }
    #pragma unroll
    for (int g = 0; g < GPB; g++) {
        float v = part[g];
        #pragma unroll
        for (int off = 16; off > 0; off >>= 1)
            v += __shfl_down_sync(0xffffffffu, v, off);
        if ((tid & 31) == 0) atomicAdd(&sout[g], v);
    }
    __syncthreads();
    if (tid < GPB) out[blockIdx.x * GPB + tid] = sout[tid];
}

// ---------------- launch ---------------------------------------------------------
extern "C" void kernel_launch(void* const* d_in, const int* in_sizes, int n_in,
                              void* d_out, int out_size)
{
    const int*   nodes    = (const int*)  d_in[0];
    const int*   sources  = (const int*)  d_in[1];
    const int*   targets  = (const int*)  d_in[2];
    const int*   batch    = (const int*)  d_in[3];
    const float* emb      = (const float*)d_in[4];
    const float* conv_w   = (const float*)d_in[5];
    const float* hidden_w = (const float*)d_in[6];
    const float* hidden_b = (const float*)d_in[7];
    const float* out_w    = (const float*)d_in[8];
    float*       out      = (float*)d_out;

    const int N = in_sizes[0];
    const int E = in_sizes[1];

    // CSR build (counters/pool buffers self-cleaned by prior call; zero-init at load)
    k_hist        <<<(E + 255) / 256, 256>>>(sources, targets, E);
    k_scanA       <<<dim3(NBLK, 2), SCAN_BLK>>>();
    k_scanB       <<<dim3(1, 2),    SCAN_BLK>>>();
    k_scanC       <<<dim3(NBLK, 2), SCAN_BLK>>>();
    k_scatter_init<<<(N * C + 255) / 256, 256>>>(sources, targets, nodes, emb, E, N);

    // 8 fused layers, ping-pong (even count -> final in buffer 0)
    const int nb = (N + 63) / 64;
    __half* xh = nullptr;
    cudaGetSymbolAddress((void**)&xh, d_xh);
    __half* xa = xh;
    __half* xb = xh + (size_t)N_NODES * C;
    for (int l = 0; l < LAYERS; l++) {
        const float* wl = conv_w + (size_t)l * 2 * C * C;
        if ((l & 1) == 0) k_layer<<<nb, 512>>>(xa, xb, wl, N);
        else              k_layer<<<nb, 512>>>(xb, xa, wl, N);
    }
    k_pool<<<(N + 255) / 256, 256>>>(batch, xa, N);

    k_mlp<<<NGRAPH / GPB, 256>>>(hidden_w, hidden_b, out_w, out);
}

// round 9
// speedup vs baseline: 1.6287x; 1.1742x over previous
#include <cuda_runtime.h>
#include <cuda_fp16.h>
#include <cstdint>

#define N_NODES 500000
#define N_EDGES 2000000
#define C       32
#define NGRAPH  1024
#define HIDDEN  1024
#define LAYERS  8

#define SCAN_BLK 256
#define ITEMS    8
#define CHUNK    (SCAN_BLK * ITEMS)                       // 2048
#define NBLK     ((N_NODES + CHUNK - 1) / CHUNK)          // 245

// ---------------- device scratch (static; zero-initialized at load) ----------
__device__ __half d_xh  [2][(size_t)N_NODES * C];         // fp16 feature ping/pong
__device__ int    d_cnt [2][N_NODES];                     // degrees (self-cleaned by scanC)
__device__ int    d_cur [2][N_NODES];                     // scatter cursors
__device__ int    d_csr [2][N_EDGES];
__device__ int4   d_meta[N_NODES];                        // {b0, d0, b1, d1}
__device__ int    d_bsum[2][NBLK];
__device__ float  d_gsum[NGRAPH * C];                     // self-cleaned by k_mlp
__device__ float  d_gcnt[NGRAPH];

// ---------------- degree histogram (d_cnt zeroed by previous scanC) -----------
__global__ void k_hist(const int* __restrict__ src, const int* __restrict__ dst, int E)
{
    int e = blockIdx.x * blockDim.x + threadIdx.x;
    if (e >= E) return;
    atomicAdd(&d_cnt[0][__ldg(dst + e)], 1);
    atomicAdd(&d_cnt[1][__ldg(src + e)], 1);
}

// ---------------- scan phase A: per-block sums --------------------------------
__global__ void k_scanA()
{
    int y = blockIdx.y;
    int base = blockIdx.x * CHUNK + threadIdx.x * ITEMS;
    int s = 0;
    #pragma unroll
    for (int j = 0; j < ITEMS; j++) {
        int i = base + j;
        if (i < N_NODES) s += d_cnt[y][i];
    }
    #pragma unroll
    for (int o = 16; o > 0; o >>= 1) s += __shfl_down_sync(0xffffffffu, s, o);
    __shared__ int sh[8];
    if ((threadIdx.x & 31) == 0) sh[threadIdx.x >> 5] = s;
    __syncthreads();
    if (threadIdx.x == 0) {
        int t = 0;
        #pragma unroll
        for (int w = 0; w < 8; w++) t += sh[w];
        d_bsum[y][blockIdx.x] = t;
    }
}

// ---------------- scan phase B: exclusive scan of block sums ------------------
__global__ void k_scanB()
{
    int y = blockIdx.y;
    int tid = threadIdx.x;
    int lane = tid & 31, warp = tid >> 5;
    int val = (tid < NBLK) ? d_bsum[y][tid] : 0;
    int incl = val;
    #pragma unroll
    for (int o = 1; o < 32; o <<= 1) {
        int t = __shfl_up_sync(0xffffffffu, incl, o);
        if (lane >= o) incl += t;
    }
    __shared__ int shw[8];
    if (lane == 31) shw[warp] = incl;
    __syncthreads();
    if (warp == 0 && lane < 8) {
        int b = shw[lane], ib = b;
        #pragma unroll
        for (int o = 1; o < 8; o <<= 1) {
            int t = __shfl_up_sync(0xffu, ib, o);
            if (lane >= o) ib += t;
        }
        shw[lane] = ib - b;
    }
    __syncthreads();
    if (tid < NBLK) d_bsum[y][tid] = shw[warp] + incl - val;
}

// ---------------- scan phase C: meta/cursors; re-zero counters ----------------
__global__ void k_scanC()
{
    int y = blockIdx.y;
    int lane = threadIdx.x & 31, warp = threadIdx.x >> 5;
    int base = blockIdx.x * CHUNK + threadIdx.x * ITEMS;

    int v[ITEMS]; int tsum = 0;
    #pragma unroll
    for (int j = 0; j < ITEMS; j++) {
        int i = base + j;
        v[j] = (i < N_NODES) ? d_cnt[y][i] : 0;
        tsum += v[j];
    }
    int incl = tsum;
    #pragma unroll
    for (int o = 1; o < 32; o <<= 1) {
        int t = __shfl_up_sync(0xffffffffu, incl, o);
        if (lane >= o) incl += t;
    }
    __shared__ int shw[8];
    if (lane == 31) shw[warp] = incl;
    __syncthreads();
    if (warp == 0 && lane < 8) {
        int b = shw[lane], ib = b;
        #pragma unroll
        for (int o = 1; o < 8; o <<= 1) {
            int t = __shfl_up_sync(0xffu, ib, o);
            if (lane >= o) ib += t;
        }
        shw[lane] = ib - b;
    }
    __syncthreads();
    int run = d_bsum[y][blockIdx.x] + shw[warp] + (incl - tsum);
    #pragma unroll
    for (int j = 0; j < ITEMS; j++) {
        int i = base + j;
        if (i < N_NODES) {
            int* mp = (int*)&d_meta[i];
            mp[y * 2 + 0] = run;          // base
            mp[y * 2 + 1] = v[j];         // degree
            d_cur[y][i]   = run;
            d_cnt[y][i]   = 0;            // self-clean for next call
            run += v[j];
        }
    }
}

// ---------------- fused CSR fill + feature init --------------------------------
__global__ void k_scatter_init(const int* __restrict__ src, const int* __restrict__ dst,
                               const int* __restrict__ nodes, const float* __restrict__ emb,
                               int E, int n)
{
    int idx = blockIdx.x * blockDim.x + threadIdx.x;
    if (idx < n * C) {
        int node = idx >> 5;
        int c    = idx & 31;
        int t    = __ldg(nodes + node);
        d_xh[0][idx] = __float2half_rn(__ldg(emb + t * C + c));
    }
    if (idx < E) {
        int s = __ldg(src + idx);
        int t = __ldg(dst + idx);
        int p = atomicAdd(&d_cur[0][t], 1);  d_csr[0][p] = s;
        int q = atomicAdd(&d_cur[1][s], 1);  d_csr[1][q] = t;
    }
}

// ---------------- mma.m16n8k16 helper -------------------------------------------
__device__ __forceinline__ void mma_16816(float* d,
                                          uint32_t a0, uint32_t a1, uint32_t a2, uint32_t a3,
                                          uint32_t b0, uint32_t b1)
{
    asm volatile(
        "mma.sync.aligned.m16n8k16.row.col.f32.f16.f16.f32 "
        "{%0,%1,%2,%3}, {%4,%5,%6,%7}, {%8,%9}, {%0,%1,%2,%3};"
        : "+f"(d[0]), "+f"(d[1]), "+f"(d[2]), "+f"(d[3])
        : "r"(a0), "r"(a1), "r"(a2), "r"(a3), "r"(b0), "r"(b1));
}

// ---------------- fused layer: 8B-lane gather -> mma -> in-register epilogue ---
// 256 threads = 8 warps; 64 nodes/block; warp gathers 8 nodes serially.
// Gather layout: lane = (rs = lane>>3: row-in-batch 0..3, cq = lane&7: channel quad).
// One uint2 LDG fetches 4 channels of one of 4 neighbor rows -> 4 rows/instr.
// Residual xv is seeded ONLY in the rs==0 group (cross-group reduction sums groups).
__global__ void __launch_bounds__(256) k_layer(const __half* __restrict__ xin,
                                               __half* __restrict__ xout,
                                               const float* __restrict__ w, int n)
{
    __shared__ __half s_wt[2][32][32];   // transposed weights: s_wt[d][j][k] = w[d][k][j]
    __shared__ __half s_h [2][64][32];   // aggregated+normalized features
    __shared__ __half s_x [64][32];      // residual

    for (int i = threadIdx.x; i < 2 * 32 * 32; i += 256) {
        int d = i >> 10, rem = i & 1023, k = rem >> 5, j = rem & 31;
        s_wt[d][j][k] = __float2half_rn(__ldg(w + d * 1024 + k * 32 + j));
    }

    const int lane = threadIdx.x & 31;
    const int warp = threadIdx.x >> 5;
    const int cq   = lane & 7;            // channel quad (4 halves = 8B)
    const int rs   = lane >> 3;           // row-in-batch 0..3
    const int blockBase = blockIdx.x * 64;
    const unsigned FULL = 0xffffffffu;

    // ---- gather phase: each warp handles 8 nodes ----
    #pragma unroll 1
    for (int ni = 0; ni < 8; ni++) {
        int nl   = warp * 8 + ni;
        int node = blockBase + nl;
        if (node < n) {
            int4 m = __ldg(&d_meta[node]);
            uint2 xr = __ldg((const uint2*)(xin + (size_t)node * C) + cq);
            float2 xa = __half22float2(*(__half2*)&xr.x);
            float2 xb = __half22float2(*(__half2*)&xr.y);
            // seed residual only in group rs==0 (groups get summed by shfl_xor)
            float f0, f1, f2, f3;
            if (rs == 0) { f0 = xa.x; f1 = xa.y; f2 = xb.x; f3 = xb.y; }
            else         { f0 = 0.f;  f1 = 0.f;  f2 = 0.f;  f3 = 0.f; }
            float g0 = f0, g1 = f1, g2 = f2, g3 = f3;

            int p0 = m.x, r0 = m.y;
            int p1 = m.z, r1 = m.w;
            while (r0 > 0 || r1 > 0) {
                int n0 = r0 < 4 ? r0 : 4;
                int n1 = r1 < 4 ? r1 : 4;
                uint2 v0 = make_uint2(0u, 0u), v1 = make_uint2(0u, 0u);
                if (rs < n0) {
                    int s = __ldg(&d_csr[0][p0 + rs]);
                    v0 = __ldg((const uint2*)(xin + (size_t)s * C) + cq);
                }
                if (rs < n1) {
                    int s = __ldg(&d_csr[1][p1 + rs]);
                    v1 = __ldg((const uint2*)(xin + (size_t)s * C) + cq);
                }
                float2 t0 = __half22float2(*(__half2*)&v0.x);
                float2 t1 = __half22float2(*(__half2*)&v0.y);
                f0 += t0.x; f1 += t0.y; f2 += t1.x; f3 += t1.y;
                t0 = __half22float2(*(__half2*)&v1.x);
                t1 = __half22float2(*(__half2*)&v1.y);
                g0 += t0.x; g1 += t0.y; g2 += t1.x; g3 += t1.y;
                p0 += n0; r0 -= n0; p1 += n1; r1 -= n1;
            }

            // reduce over the 4 row-groups (lanes xor 8, 16)
            f0 += __shfl_xor_sync(FULL, f0, 8);  f0 += __shfl_xor_sync(FULL, f0, 16);
            f1 += __shfl_xor_sync(FULL, f1, 8);  f1 += __shfl_xor_sync(FULL, f1, 16);
            f2 += __shfl_xor_sync(FULL, f2, 8);  f2 += __shfl_xor_sync(FULL, f2, 16);
            f3 += __shfl_xor_sync(FULL, f3, 8);  f3 += __shfl_xor_sync(FULL, f3, 16);
            g0 += __shfl_xor_sync(FULL, g0, 8);  g0 += __shfl_xor_sync(FULL, g0, 16);
            g1 += __shfl_xor_sync(FULL, g1, 8);  g1 += __shfl_xor_sync(FULL, g1, 16);
            g2 += __shfl_xor_sync(FULL, g2, 8);  g2 += __shfl_xor_sync(FULL, g2, 16);
            g3 += __shfl_xor_sync(FULL, g3, 8);  g3 += __shfl_xor_sync(FULL, g3, 16);

            float nf = __fdividef(1.f, 1.f + (float)m.y);
            float nb = __fdividef(1.f, 1.f + (float)m.w);

            if (rs == 0) {
                __half2 hf0 = __floats2half2_rn(f0 * nf, f1 * nf);
                __half2 hf1 = __floats2half2_rn(f2 * nf, f3 * nf);
                __half2 hb0 = __floats2half2_rn(g0 * nb, g1 * nb);
                __half2 hb1 = __floats2half2_rn(g2 * nb, g3 * nb);
                uint2 pf; pf.x = *(uint32_t*)&hf0; pf.y = *(uint32_t*)&hf1;
                uint2 pb; pb.x = *(uint32_t*)&hb0; pb.y = *(uint32_t*)&hb1;
                *(uint2*)&s_h[0][nl][cq * 4] = pf;
                *(uint2*)&s_h[1][nl][cq * 4] = pb;
                *(uint2*)&s_x[nl][cq * 4]    = xr;
            }
        } else if (rs == 0) {
            uint2 z = make_uint2(0u, 0u);
            *(uint2*)&s_h[0][nl][cq * 4] = z;
            *(uint2*)&s_h[1][nl][cq * 4] = z;
            *(uint2*)&s_x[nl][cq * 4]    = z;
        }
    }
    __syncthreads();

    // ---- GEMM + epilogue: warps 0..3, warp = m-tile (16 nodes), both dirs ----
    if (warp < 4) {
        const int g  = lane >> 2;
        const int t  = lane & 3;
        const int m0 = warp * 16;

        float acc0[4][4], acc1[4][4];
        #pragma unroll
        for (int nt = 0; nt < 4; nt++)
            #pragma unroll
            for (int i = 0; i < 4; i++) { acc0[nt][i] = 0.f; acc1[nt][i] = 0.f; }

        #pragma unroll
        for (int kt = 0; kt < 32; kt += 16) {
            // direction 0
            uint32_t a0 = *(const uint32_t*)&s_h[0][m0 + g    ][kt + t * 2];
            uint32_t a1 = *(const uint32_t*)&s_h[0][m0 + g + 8][kt + t * 2];
            uint32_t a2 = *(const uint32_t*)&s_h[0][m0 + g    ][kt + t * 2 + 8];
            uint32_t a3 = *(const uint32_t*)&s_h[0][m0 + g + 8][kt + t * 2 + 8];
            #pragma unroll
            for (int nt = 0; nt < 4; nt++) {
                uint32_t b0 = *(const uint32_t*)&s_wt[0][nt * 8 + g][kt + t * 2];
                uint32_t b1 = *(const uint32_t*)&s_wt[0][nt * 8 + g][kt + t * 2 + 8];
                mma_16816(acc0[nt], a0, a1, a2, a3, b0, b1);
            }
            // direction 1
            a0 = *(const uint32_t*)&s_h[1][m0 + g    ][kt + t * 2];
            a1 = *(const uint32_t*)&s_h[1][m0 + g + 8][kt + t * 2];
            a2 = *(const uint32_t*)&s_h[1][m0 + g    ][kt + t * 2 + 8];
            a3 = *(const uint32_t*)&s_h[1][m0 + g + 8][kt + t * 2 + 8];
            #pragma unroll
            for (int nt = 0; nt < 4; nt++) {
                uint32_t b0 = *(const uint32_t*)&s_wt[1][nt * 8 + g][kt + t * 2];
                uint32_t b1 = *(const uint32_t*)&s_wt[1][nt * 8 + g][kt + t * 2 + 8];
                mma_16816(acc1[nt], a0, a1, a2, a3, b0, b1);
            }
        }

        // epilogue: out = x + relu(A0) + relu(A1); fragment rows m0+g, m0+g+8
        int node0 = blockBase + m0 + g;
        int node1 = node0 + 8;
        #pragma unroll
        for (int nt = 0; nt < 4; nt++) {
            int col = nt * 8 + t * 2;
            float2 xv0 = __half22float2(*(__half2*)&s_x[m0 + g    ][col]);
            float2 xv1 = __half22float2(*(__half2*)&s_x[m0 + g + 8][col]);
            float o00 = xv0.x + fmaxf(acc0[nt][0], 0.f) + fmaxf(acc1[nt][0], 0.f);
            float o01 = xv0.y + fmaxf(acc0[nt][1], 0.f) + fmaxf(acc1[nt][1], 0.f);
            float o10 = xv1.x + fmaxf(acc0[nt][2], 0.f) + fmaxf(acc1[nt][2], 0.f);
            float o11 = xv1.y + fmaxf(acc0[nt][3], 0.f) + fmaxf(acc1[nt][3], 0.f);
            if (node0 < n)
                *(__half2*)&xout[(size_t)node0 * C + col] = __floats2half2_rn(o00, o01);
            if (node1 < n)
                *(__half2*)&xout[(size_t)node1 * C + col] = __floats2half2_rn(o10, o11);
        }
    }
}

// ---------------- pooling: per-graph sum + count (batch sorted) ----------------
__global__ void k_pool(const int* __restrict__ batch, const __half* __restrict__ x, int n)
{
    int lane = threadIdx.x & 31;
    int warp = threadIdx.x >> 5;
    int base = blockIdx.x * 256 + warp * 32;

    float acc = 0.f;
    int cur = -1, run = 0;
    for (int j = 0; j < 32; j++) {
        int node = base + j;
        if (node >= n) break;
        int b = __ldg(batch + node);
        float v = __half2float(__ldg(x + (size_t)node * C + lane));
        if (b != cur) {
            if (cur >= 0) {
                atomicAdd(&d_gsum[cur * C + lane], acc);
                if (lane == 0) atomicAdd(&d_gcnt[cur], (float)run);
            }
            cur = b; acc = 0.f; run = 0;
        }
        acc += v; run++;
    }
    if (cur >= 0) {
        atomicAdd(&d_gsum[cur * C + lane], acc);
        if (lane == 0) atomicAdd(&d_gcnt[cur], (float)run);
    }
}

// ---------------- MLP head: 8 graphs per block; self-cleans pool buffers -------
#define GPB 8
__global__ void k_mlp(const float* __restrict__ hw, const float* __restrict__ hb,
                      const float* __restrict__ ow, float* __restrict__ out)
{
    __shared__ float gs[GPB][C];
    __shared__ float sout[GPB];
    int tid = threadIdx.x;
    if (tid < GPB * C) {
        int g = tid >> 5, c = tid & 31;
        int gb = blockIdx.x * GPB + g;
        gs[g][c] = d_gsum[gb * C + c] / d_gcnt[gb];
    }
    if (tid < GPB) sout[tid] = 0.f;
    __syncthreads();
    // self-clean for next kernel_launch call
    if (tid < GPB * C) {
        int g = tid >> 5, c = tid & 31;
        d_gsum[(blockIdx.x * GPB + g) * C + c] = 0.f;
    }
    if (tid < GPB) d_gcnt[blockIdx.x * GPB + tid] = 0.f;

    float part[GPB];
    #pragma unroll
    for (int g = 0; g < GPB; g++) part[g] = 0.f;

    for (int j = tid; j < HIDDEN; j += 256) {
        float h[GPB];
        float bj = __ldg(hb + j);
        #pragma unroll
        for (int g = 0; g < GPB; g++) h[g] = bj;
        #pragma unroll
        for (int k = 0; k < C; k++) {
            float wkj = __ldg(hw + k * HIDDEN + j);
            #pragma unroll
            for (int g = 0; g < GPB; g++)
                h[g] = fmaf(gs[g][k], wkj, h[g]);
        }
        float oj = __ldg(ow + j);
        #pragma unroll
        for (int g = 0; g < GPB; g++)
            part[g] += fmaxf(h[g], 0.f) * oj;
    }
    #pragma unroll
    for (int g = 0; g < GPB; g++) {
        float v = part[g];
        #pragma unroll
        for (int off = 16; off > 0; off >>= 1)
            v += __shfl_down_sync(0xffffffffu, v, off);
        if ((tid & 31) == 0) atomicAdd(&sout[g], v);
    }
    __syncthreads();
    if (tid < GPB) out[blockIdx.x * GPB + tid] = sout[tid];
}

// ---------------- launch ---------------------------------------------------------
extern "C" void kernel_launch(void* const* d_in, const int* in_sizes, int n_in,
                              void* d_out, int out_size)
{
    const int*   nodes    = (const int*)  d_in[0];
    const int*   sources  = (const int*)  d_in[1];
    const int*   targets  = (const int*)  d_in[2];
    const int*   batch    = (const int*)  d_in[3];
    const float* emb      = (const float*)d_in[4];
    const float* conv_w   = (const float*)d_in[5];
    const float* hidden_w = (const float*)d_in[6];
    const float* hidden_b = (const float*)d_in[7];
    const float* out_w    = (const float*)d_in[8];
    float*       out      = (float*)d_out;

    const int N = in_sizes[0];
    const int E = in_sizes[1];

    // CSR build (counters/pool buffers self-cleaned by prior call; zero-init at load)
    k_hist        <<<(E + 255) / 256, 256>>>(sources, targets, E);
    k_scanA       <<<dim3(NBLK, 2), SCAN_BLK>>>();
    k_scanB       <<<dim3(1, 2),    SCAN_BLK>>>();
    k_scanC       <<<dim3(NBLK, 2), SCAN_BLK>>>();
    k_scatter_init<<<(N * C + 255) / 256, 256>>>(sources, targets, nodes, emb, E, N);

    // 8 fused layers, ping-pong (even count -> final in buffer 0)
    const int nb = (N + 63) / 64;
    __half* xh = nullptr;
    cudaGetSymbolAddress((void**)&xh, d_xh);
    __half* xa = xh;
    __half* xb = xh + (size_t)N_NODES * C;
    for (int l = 0; l < LAYERS; l++) {
        const float* wl = conv_w + (size_t)l * 2 * C * C;
        if ((l & 1) == 0) k_layer<<<nb, 256>>>(xa, xb, wl, N);
        else              k_layer<<<nb, 256>>>(xb, xa, wl, N);
    }
    k_pool<<<(N + 255) / 256, 256>>>(batch, xa, N);

    k_mlp<<<NGRAPH / GPB, 256>>>(hidden_w, hidden_b, out_w, out);
}

// round 10
// speedup vs baseline: 1.8859x; 1.1579x over previous
#include <cuda_runtime.h>
#include <cuda_fp16.h>
#include <cstdint>

#define N_NODES 500000
#define N_EDGES 2000000
#define C       32
#define NGRAPH  1024
#define HIDDEN  1024
#define LAYERS  8

#define SCAN_BLK 256
#define ITEMS    8
#define CHUNK    (SCAN_BLK * ITEMS)                       // 2048
#define NBLK     ((N_NODES + CHUNK - 1) / CHUNK)          // 245

// ---------------- device scratch (static; zero-initialized at load) ----------
__device__ __half d_xh  [2][(size_t)N_NODES * C];         // fp16 feature ping/pong
__device__ int    d_cnt [2][N_NODES];                     // degrees (self-cleaned by scanC)
__device__ int    d_cur [2][N_NODES];                     // scatter cursors
__device__ int    d_csr [2][N_EDGES];
__device__ int4   d_meta[N_NODES];                        // {b0, d0, b1, d1}
__device__ int    d_bsum[2][NBLK];
__device__ float  d_gsum[NGRAPH * C];                     // self-cleaned by k_mlp
__device__ float  d_gcnt[NGRAPH];

// ---------------- degree histogram (d_cnt zeroed by previous scanC) -----------
__global__ void k_hist(const int* __restrict__ src, const int* __restrict__ dst, int E)
{
    int e = blockIdx.x * blockDim.x + threadIdx.x;
    if (e >= E) return;
    atomicAdd(&d_cnt[0][__ldg(dst + e)], 1);
    atomicAdd(&d_cnt[1][__ldg(src + e)], 1);
}

// ---------------- scan phase A: per-block sums --------------------------------
__global__ void k_scanA()
{
    int y = blockIdx.y;
    int base = blockIdx.x * CHUNK + threadIdx.x * ITEMS;
    int s = 0;
    #pragma unroll
    for (int j = 0; j < ITEMS; j++) {
        int i = base + j;
        if (i < N_NODES) s += d_cnt[y][i];
    }
    #pragma unroll
    for (int o = 16; o > 0; o >>= 1) s += __shfl_down_sync(0xffffffffu, s, o);
    __shared__ int sh[8];
    if ((threadIdx.x & 31) == 0) sh[threadIdx.x >> 5] = s;
    __syncthreads();
    if (threadIdx.x == 0) {
        int t = 0;
        #pragma unroll
        for (int w = 0; w < 8; w++) t += sh[w];
        d_bsum[y][blockIdx.x] = t;
    }
}

// ---------------- scan phase B: exclusive scan of block sums ------------------
__global__ void k_scanB()
{
    int y = blockIdx.y;
    int tid = threadIdx.x;
    int lane = tid & 31, warp = tid >> 5;
    int val = (tid < NBLK) ? d_bsum[y][tid] : 0;
    int incl = val;
    #pragma unroll
    for (int o = 1; o < 32; o <<= 1) {
        int t = __shfl_up_sync(0xffffffffu, incl, o);
        if (lane >= o) incl += t;
    }
    __shared__ int shw[8];
    if (lane == 31) shw[warp] = incl;
    __syncthreads();
    if (warp == 0 && lane < 8) {
        int b = shw[lane], ib = b;
        #pragma unroll
        for (int o = 1; o < 8; o <<= 1) {
            int t = __shfl_up_sync(0xffu, ib, o);
            if (lane >= o) ib += t;
        }
        shw[lane] = ib - b;
    }
    __syncthreads();
    if (tid < NBLK) d_bsum[y][tid] = shw[warp] + incl - val;
}

// ---------------- scan phase C: meta/cursors; re-zero counters ----------------
__global__ void k_scanC()
{
    int y = blockIdx.y;
    int lane = threadIdx.x & 31, warp = threadIdx.x >> 5;
    int base = blockIdx.x * CHUNK + threadIdx.x * ITEMS;

    int v[ITEMS]; int tsum = 0;
    #pragma unroll
    for (int j = 0; j < ITEMS; j++) {
        int i = base + j;
        v[j] = (i < N_NODES) ? d_cnt[y][i] : 0;
        tsum += v[j];
    }
    int incl = tsum;
    #pragma unroll
    for (int o = 1; o < 32; o <<= 1) {
        int t = __shfl_up_sync(0xffffffffu, incl, o);
        if (lane >= o) incl += t;
    }
    __shared__ int shw[8];
    if (lane == 31) shw[warp] = incl;
    __syncthreads();
    if (warp == 0 && lane < 8) {
        int b = shw[lane], ib = b;
        #pragma unroll
        for (int o = 1; o < 8; o <<= 1) {
            int t = __shfl_up_sync(0xffu, ib, o);
            if (lane >= o) ib += t;
        }
        shw[lane] = ib - b;
    }
    __syncthreads();
    int run = d_bsum[y][blockIdx.x] + shw[warp] + (incl - tsum);
    #pragma unroll
    for (int j = 0; j < ITEMS; j++) {
        int i = base + j;
        if (i < N_NODES) {
            int* mp = (int*)&d_meta[i];
            mp[y * 2 + 0] = run;          // base
            mp[y * 2 + 1] = v[j];         // degree
            d_cur[y][i]   = run;
            d_cnt[y][i]   = 0;            // self-clean for next call
            run += v[j];
        }
    }
}

// ---------------- fused CSR fill + feature init --------------------------------
__global__ void k_scatter_init(const int* __restrict__ src, const int* __restrict__ dst,
                               const int* __restrict__ nodes, const float* __restrict__ emb,
                               int E, int n)
{
    int idx = blockIdx.x * blockDim.x + threadIdx.x;
    if (idx < n * C) {
        int node = idx >> 5;
        int c    = idx & 31;
        int t    = __ldg(nodes + node);
        d_xh[0][idx] = __float2half_rn(__ldg(emb + t * C + c));
    }
    if (idx < E) {
        int s = __ldg(src + idx);
        int t = __ldg(dst + idx);
        int p = atomicAdd(&d_cur[0][t], 1);  d_csr[0][p] = s;
        int q = atomicAdd(&d_cur[1][s], 1);  d_csr[1][q] = t;
    }
}

// ---------------- mma.m16n8k16 helper -------------------------------------------
__device__ __forceinline__ void mma_16816(float* d,
                                          uint32_t a0, uint32_t a1, uint32_t a2, uint32_t a3,
                                          uint32_t b0, uint32_t b1)
{
    asm volatile(
        "mma.sync.aligned.m16n8k16.row.col.f32.f16.f16.f32 "
        "{%0,%1,%2,%3}, {%4,%5,%6,%7}, {%8,%9}, {%0,%1,%2,%3};"
        : "+f"(d[0]), "+f"(d[1]), "+f"(d[2]), "+f"(d[3])
        : "r"(a0), "r"(a1), "r"(a2), "r"(a3), "r"(b0), "r"(b1));
}

// ---------------- fused layer: smem-staged CSR -> 8B-lane gather -> mma --------
// 256 threads = 8 warps; 64 nodes/block. Per block, the contiguous CSR slices
// of its 64 nodes (both dirs) + their meta records are staged into smem, so the
// per-node chain is: smem meta -> smem idx -> ONE global row gather.
#define CAPI 512
__global__ void __launch_bounds__(256) k_layer(const __half* __restrict__ xin,
                                               __half* __restrict__ xout,
                                               const float* __restrict__ w, int n)
{
    __shared__ __half s_wt[2][32][32];   // 4 KB transposed weights
    __shared__ __half s_h [2][64][32];   // 8 KB aggregated features
    __shared__ __half s_x [64][32];      // 4 KB residual
    __shared__ int4   s_meta[64];        // 1 KB node meta
    __shared__ int    s_idx[2][CAPI];    // 4 KB CSR slices

    const int tid  = threadIdx.x;
    const int lane = tid & 31;
    const int warp = tid >> 5;
    const int cq   = lane & 7;            // channel quad (4 halves = 8 B)
    const int rs   = lane >> 3;           // row-in-batch 0..3
    const int blockBase = blockIdx.x * 64;
    const int lastLocal = min(64, n - blockBase);   // valid nodes in block (>=1)
    const unsigned FULL = 0xffffffffu;

    // stage weights (transposed) + meta
    for (int i = tid; i < 2 * 32 * 32; i += 256) {
        int d = i >> 10, rem = i & 1023, k = rem >> 5, j = rem & 31;
        s_wt[d][j][k] = __float2half_rn(__ldg(w + d * 1024 + k * 32 + j));
    }
    if (tid < 64) {
        s_meta[tid] = (tid < lastLocal) ? __ldg(&d_meta[blockBase + tid])
                                        : make_int4(0, 0, 0, 0);
    }
    __syncthreads();

    // stage contiguous CSR slices for this block's nodes
    const int4 mF = s_meta[0];
    const int4 mL = s_meta[lastLocal - 1];
    const int beg0 = mF.x, len0 = mL.x + mL.y - mF.x;
    const int beg1 = mF.z, len1 = mL.z + mL.w - mF.z;
    for (int i = tid; i < min(len0, CAPI); i += 256) s_idx[0][i] = __ldg(&d_csr[0][beg0 + i]);
    for (int i = tid; i < min(len1, CAPI); i += 256) s_idx[1][i] = __ldg(&d_csr[1][beg1 + i]);
    __syncthreads();

    // ---- gather phase: each warp handles 8 nodes ----
    #pragma unroll 1
    for (int ni = 0; ni < 8; ni++) {
        int nl   = warp * 8 + ni;
        int node = blockBase + nl;
        if (nl < lastLocal) {
            int4 m = s_meta[nl];
            int o0 = m.x - beg0, o1 = m.z - beg1;
            int r0 = m.y,        r1 = m.w;

            uint2 xr = __ldg((const uint2*)(xin + (size_t)node * C) + cq);
            float2 xa = __half22float2(*(__half2*)&xr.x);
            float2 xb = __half22float2(*(__half2*)&xr.y);
            float f0, f1, f2, f3;
            if (rs == 0) { f0 = xa.x; f1 = xa.y; f2 = xb.x; f3 = xb.y; }
            else         { f0 = 0.f;  f1 = 0.f;  f2 = 0.f;  f3 = 0.f; }
            float g0 = f0, g1 = f1, g2 = f2, g3 = f3;

            // first batch (covers deg<=4 common case, straight-line)
            int n0 = r0 < 4 ? r0 : 4;
            int n1 = r1 < 4 ? r1 : 4;
            uint2 v0 = make_uint2(0u, 0u), v1 = make_uint2(0u, 0u);
            if (rs < n0) {
                int p = o0 + rs;
                int s = (p < CAPI) ? s_idx[0][p] : __ldg(&d_csr[0][beg0 + p]);
                v0 = __ldg((const uint2*)(xin + (size_t)s * C) + cq);
            }
            if (rs < n1) {
                int p = o1 + rs;
                int s = (p < CAPI) ? s_idx[1][p] : __ldg(&d_csr[1][beg1 + p]);
                v1 = __ldg((const uint2*)(xin + (size_t)s * C) + cq);
            }
            {
                float2 t0 = __half22float2(*(__half2*)&v0.x);
                float2 t1 = __half22float2(*(__half2*)&v0.y);
                f0 += t0.x; f1 += t0.y; f2 += t1.x; f3 += t1.y;
                t0 = __half22float2(*(__half2*)&v1.x);
                t1 = __half22float2(*(__half2*)&v1.y);
                g0 += t0.x; g1 += t0.y; g2 += t1.x; g3 += t1.y;
            }

            // rare remainder (deg>4)
            int p0 = n0, p1 = n1;
            while (p0 < r0 || p1 < r1) {
                n0 = r0 - p0; if (n0 < 0) n0 = 0; if (n0 > 4) n0 = 4;
                n1 = r1 - p1; if (n1 < 0) n1 = 0; if (n1 > 4) n1 = 4;
                v0 = make_uint2(0u, 0u); v1 = make_uint2(0u, 0u);
                if (rs < n0) {
                    int p = o0 + p0 + rs;
                    int s = (p < CAPI) ? s_idx[0][p] : __ldg(&d_csr[0][beg0 + p]);
                    v0 = __ldg((const uint2*)(xin + (size_t)s * C) + cq);
                }
                if (rs < n1) {
                    int p = o1 + p1 + rs;
                    int s = (p < CAPI) ? s_idx[1][p] : __ldg(&d_csr[1][beg1 + p]);
                    v1 = __ldg((const uint2*)(xin + (size_t)s * C) + cq);
                }
                float2 t0 = __half22float2(*(__half2*)&v0.x);
                float2 t1 = __half22float2(*(__half2*)&v0.y);
                f0 += t0.x; f1 += t0.y; f2 += t1.x; f3 += t1.y;
                t0 = __half22float2(*(__half2*)&v1.x);
                t1 = __half22float2(*(__half2*)&v1.y);
                g0 += t0.x; g1 += t0.y; g2 += t1.x; g3 += t1.y;
                p0 += n0; p1 += n1;
            }

            // reduce over the 4 row-groups (lanes xor 8, 16)
            f0 += __shfl_xor_sync(FULL, f0, 8);  f0 += __shfl_xor_sync(FULL, f0, 16);
            f1 += __shfl_xor_sync(FULL, f1, 8);  f1 += __shfl_xor_sync(FULL, f1, 16);
            f2 += __shfl_xor_sync(FULL, f2, 8);  f2 += __shfl_xor_sync(FULL, f2, 16);
            f3 += __shfl_xor_sync(FULL, f3, 8);  f3 += __shfl_xor_sync(FULL, f3, 16);
            g0 += __shfl_xor_sync(FULL, g0, 8);  g0 += __shfl_xor_sync(FULL, g0, 16);
            g1 += __shfl_xor_sync(FULL, g1, 8);  g1 += __shfl_xor_sync(FULL, g1, 16);
            g2 += __shfl_xor_sync(FULL, g2, 8);  g2 += __shfl_xor_sync(FULL, g2, 16);
            g3 += __shfl_xor_sync(FULL, g3, 8);  g3 += __shfl_xor_sync(FULL, g3, 16);

            float nf = __fdividef(1.f, 1.f + (float)r0);
            float nb = __fdividef(1.f, 1.f + (float)r1);

            if (rs == 0) {
                __half2 hf0 = __floats2half2_rn(f0 * nf, f1 * nf);
                __half2 hf1 = __floats2half2_rn(f2 * nf, f3 * nf);
                __half2 hb0 = __floats2half2_rn(g0 * nb, g1 * nb);
                __half2 hb1 = __floats2half2_rn(g2 * nb, g3 * nb);
                uint2 pf; pf.x = *(uint32_t*)&hf0; pf.y = *(uint32_t*)&hf1;
                uint2 pb; pb.x = *(uint32_t*)&hb0; pb.y = *(uint32_t*)&hb1;
                *(uint2*)&s_h[0][nl][cq * 4] = pf;
                *(uint2*)&s_h[1][nl][cq * 4] = pb;
                *(uint2*)&s_x[nl][cq * 4]    = xr;
            }
        } else if (rs == 0) {
            uint2 z = make_uint2(0u, 0u);
            *(uint2*)&s_h[0][nl][cq * 4] = z;
            *(uint2*)&s_h[1][nl][cq * 4] = z;
            *(uint2*)&s_x[nl][cq * 4]    = z;
        }
    }
    __syncthreads();

    // ---- GEMM + epilogue: warps 0..3, warp = m-tile (16 nodes), both dirs ----
    if (warp < 4) {
        const int g  = lane >> 2;
        const int t  = lane & 3;
        const int m0 = warp * 16;

        float acc0[4][4], acc1[4][4];
        #pragma unroll
        for (int nt = 0; nt < 4; nt++)
            #pragma unroll
            for (int i = 0; i < 4; i++) { acc0[nt][i] = 0.f; acc1[nt][i] = 0.f; }

        #pragma unroll
        for (int kt = 0; kt < 32; kt += 16) {
            uint32_t a0 = *(const uint32_t*)&s_h[0][m0 + g    ][kt + t * 2];
            uint32_t a1 = *(const uint32_t*)&s_h[0][m0 + g + 8][kt + t * 2];
            uint32_t a2 = *(const uint32_t*)&s_h[0][m0 + g    ][kt + t * 2 + 8];
            uint32_t a3 = *(const uint32_t*)&s_h[0][m0 + g + 8][kt + t * 2 + 8];
            #pragma unroll
            for (int nt = 0; nt < 4; nt++) {
                uint32_t b0 = *(const uint32_t*)&s_wt[0][nt * 8 + g][kt + t * 2];
                uint32_t b1 = *(const uint32_t*)&s_wt[0][nt * 8 + g][kt + t * 2 + 8];
                mma_16816(acc0[nt], a0, a1, a2, a3, b0, b1);
            }
            a0 = *(const uint32_t*)&s_h[1][m0 + g    ][kt + t * 2];
            a1 = *(const uint32_t*)&s_h[1][m0 + g + 8][kt + t * 2];
            a2 = *(const uint32_t*)&s_h[1][m0 + g    ][kt + t * 2 + 8];
            a3 = *(const uint32_t*)&s_h[1][m0 + g + 8][kt + t * 2 + 8];
            #pragma unroll
            for (int nt = 0; nt < 4; nt++) {
                uint32_t b0 = *(const uint32_t*)&s_wt[1][nt * 8 + g][kt + t * 2];
                uint32_t b1 = *(const uint32_t*)&s_wt[1][nt * 8 + g][kt + t * 2 + 8];
                mma_16816(acc1[nt], a0, a1, a2, a3, b0, b1);
            }
        }

        int node0 = blockBase + m0 + g;
        int node1 = node0 + 8;
        #pragma unroll
        for (int nt = 0; nt < 4; nt++) {
            int col = nt * 8 + t * 2;
            float2 xv0 = __half22float2(*(__half2*)&s_x[m0 + g    ][col]);
            float2 xv1 = __half22float2(*(__half2*)&s_x[m0 + g + 8][col]);
            float o00 = xv0.x + fmaxf(acc0[nt][0], 0.f) + fmaxf(acc1[nt][0], 0.f);
            float o01 = xv0.y + fmaxf(acc0[nt][1], 0.f) + fmaxf(acc1[nt][1], 0.f);
            float o10 = xv1.x + fmaxf(acc0[nt][2], 0.f) + fmaxf(acc1[nt][2], 0.f);
            float o11 = xv1.y + fmaxf(acc0[nt][3], 0.f) + fmaxf(acc1[nt][3], 0.f);
            if (node0 < n)
                *(__half2*)&xout[(size_t)node0 * C + col] = __floats2half2_rn(o00, o01);
            if (node1 < n)
                *(__half2*)&xout[(size_t)node1 * C + col] = __floats2half2_rn(o10, o11);
        }
    }
}

// ---------------- pooling: per-graph sum + count (batch sorted) ----------------
__global__ void k_pool(const int* __restrict__ batch, const __half* __restrict__ x, int n)
{
    int lane = threadIdx.x & 31;
    int warp = threadIdx.x >> 5;
    int base = blockIdx.x * 256 + warp * 32;

    float acc = 0.f;
    int cur = -1, run = 0;
    for (int j = 0; j < 32; j++) {
        int node = base + j;
        if (node >= n) break;
        int b = __ldg(batch + node);
        float v = __half2float(__ldg(x + (size_t)node * C + lane));
        if (b != cur) {
            if (cur >= 0) {
                atomicAdd(&d_gsum[cur * C + lane], acc);
                if (lane == 0) atomicAdd(&d_gcnt[cur], (float)run);
            }
            cur = b; acc = 0.f; run = 0;
        }
        acc += v; run++;
    }
    if (cur >= 0) {
        atomicAdd(&d_gsum[cur * C + lane], acc);
        if (lane == 0) atomicAdd(&d_gcnt[cur], (float)run);
    }
}

// ---------------- MLP head: 8 graphs per block; self-cleans pool buffers -------
#define GPB 8
__global__ void k_mlp(const float* __restrict__ hw, const float* __restrict__ hb,
                      const float* __restrict__ ow, float* __restrict__ out)
{
    __shared__ float gs[GPB][C];
    __shared__ float sout[GPB];
    int tid = threadIdx.x;
    if (tid < GPB * C) {
        int g = tid >> 5, c = tid & 31;
        int gb = blockIdx.x * GPB + g;
        gs[g][c] = d_gsum[gb * C + c] / d_gcnt[gb];
    }
    if (tid < GPB) sout[tid] = 0.f;
    __syncthreads();
    // self-clean for next kernel_launch call
    if (tid < GPB * C) {
        int g = tid >> 5, c = tid & 31;
        d_gsum[(blockIdx.x * GPB + g) * C + c] = 0.f;
    }
    if (tid < GPB) d_gcnt[blockIdx.x * GPB + tid] = 0.f;

    float part[GPB];
    #pragma unroll
    for (int g = 0; g < GPB; g++) part[g] = 0.f;

    for (int j = tid; j < HIDDEN; j += 256) {
        float h[GPB];
        float bj = __ldg(hb + j);
        #pragma unroll
        for (int g = 0; g < GPB; g++) h[g] = bj;
        #pragma unroll
        for (int k = 0; k < C; k++) {
            float wkj = __ldg(hw + k * HIDDEN + j);
            #pragma unroll
            for (int g = 0; g < GPB; g++)
                h[g] = fmaf(gs[g][k], wkj, h[g]);
        }
        float oj = __ldg(ow + j);
        #pragma unroll
        for (int g = 0; g < GPB; g++)
            part[g] += fmaxf(h[g], 0.f) * oj;
    }
    #pragma unroll
    for (int g = 0; g < GPB; g++) {
        float v = part[g];
        #pragma unroll
        for (int off = 16; off > 0; off >>= 1)
            v += __shfl_down_sync(0xffffffffu, v, off);
        if ((tid & 31) == 0) atomicAdd(&sout[g], v);
    }
    __syncthreads();
    if (tid < GPB) out[blockIdx.x * GPB + tid] = sout[tid];
}

// ---------------- launch ---------------------------------------------------------
extern "C" void kernel_launch(void* const* d_in, const int* in_sizes, int n_in,
                              void* d_out, int out_size)
{
    const int*   nodes    = (const int*)  d_in[0];
    const int*   sources  = (const int*)  d_in[1];
    const int*   targets  = (const int*)  d_in[2];
    const int*   batch    = (const int*)  d_in[3];
    const float* emb      = (const float*)d_in[4];
    const float* hidden_w = (const float*)d_in[6];
    const float* hidden_b = (const float*)d_in[7];
    const float* out_w    = (const float*)d_in[8];
    const float* conv_w   = (const float*)d_in[5];
    float*       out      = (float*)d_out;

    const int N = in_sizes[0];
    const int E = in_sizes[1];

    // CSR build (counters/pool buffers self-cleaned by prior call; zero-init at load)
    k_hist        <<<(E + 255) / 256, 256>>>(sources, targets, E);
    k_scanA       <<<dim3(NBLK, 2), SCAN_BLK>>>();
    k_scanB       <<<dim3(1, 2),    SCAN_BLK>>>();
    k_scanC       <<<dim3(NBLK, 2), SCAN_BLK>>>();
    k_scatter_init<<<(N * C + 255) / 256, 256>>>(sources, targets, nodes, emb, E, N);

    // 8 fused layers, ping-pong (even count -> final in buffer 0)
    const int nb = (N + 63) / 64;
    __half* xh = nullptr;
    cudaGetSymbolAddress((void**)&xh, d_xh);
    __half* xa = xh;
    __half* xb = xh + (size_t)N_NODES * C;
    for (int l = 0; l < LAYERS; l++) {
        const float* wl = conv_w + (size_t)l * 2 * C * C;
        if ((l & 1) == 0) k_layer<<<nb, 256>>>(xa, xb, wl, N);
        else              k_layer<<<nb, 256>>>(xb, xa, wl, N);
    }
    k_pool<<<(N + 255) / 256, 256>>>(batch, xa, N);

    k_mlp<<<NGRAPH / GPB, 256>>>(hidden_w, hidden_b, out_w, out);
}

// round 11
// speedup vs baseline: 1.9792x; 1.0495x over previous
#include <cuda_runtime.h>
#include <cuda_fp16.h>
#include <cstdint>

#define N_NODES 500000
#define N_EDGES 2000000
#define C       32
#define NGRAPH  1024
#define HIDDEN  1024
#define LAYERS  8

#define SCAN_BLK 256
#define ITEMS    8
#define CHUNK    (SCAN_BLK * ITEMS)                       // 2048
#define NBLK     ((N_NODES + CHUNK - 1) / CHUNK)          // 245

// ---------------- device scratch (static; zero-initialized at load) ----------
__device__ __half d_xh  [2][(size_t)N_NODES * C];         // fp16 feature ping/pong
__device__ int    d_cnt [2][N_NODES];                     // degrees (self-cleaned by scanC)
__device__ int    d_cur [2][N_NODES];                     // scatter cursors
__device__ int    d_csr [2][N_EDGES];
__device__ int4   d_meta[N_NODES];                        // {b0, d0, b1, d1}
__device__ int    d_bsum[2][NBLK];
__device__ float  d_gsum[NGRAPH * C];                     // self-cleaned by k_mlp
__device__ float  d_gcnt[NGRAPH];

// ---------------- degree histogram (d_cnt zeroed by previous scanC) -----------
__global__ void k_hist(const int* __restrict__ src, const int* __restrict__ dst, int E)
{
    int e = blockIdx.x * blockDim.x + threadIdx.x;
    if (e >= E) return;
    atomicAdd(&d_cnt[0][__ldg(dst + e)], 1);
    atomicAdd(&d_cnt[1][__ldg(src + e)], 1);
}

// ---------------- scan phase A: per-block sums --------------------------------
__global__ void k_scanA()
{
    int y = blockIdx.y;
    int base = blockIdx.x * CHUNK + threadIdx.x * ITEMS;
    int s = 0;
    #pragma unroll
    for (int j = 0; j < ITEMS; j++) {
        int i = base + j;
        if (i < N_NODES) s += d_cnt[y][i];
    }
    #pragma unroll
    for (int o = 16; o > 0; o >>= 1) s += __shfl_down_sync(0xffffffffu, s, o);
    __shared__ int sh[8];
    if ((threadIdx.x & 31) == 0) sh[threadIdx.x >> 5] = s;
    __syncthreads();
    if (threadIdx.x == 0) {
        int t = 0;
        #pragma unroll
        for (int w = 0; w < 8; w++) t += sh[w];
        d_bsum[y][blockIdx.x] = t;
    }
}

// ---------------- scan phase B: exclusive scan of block sums ------------------
__global__ void k_scanB()
{
    int y = blockIdx.y;
    int tid = threadIdx.x;
    int lane = tid & 31, warp = tid >> 5;
    int val = (tid < NBLK) ? d_bsum[y][tid] : 0;
    int incl = val;
    #pragma unroll
    for (int o = 1; o < 32; o <<= 1) {
        int t = __shfl_up_sync(0xffffffffu, incl, o);
        if (lane >= o) incl += t;
    }
    __shared__ int shw[8];
    if (lane == 31) shw[warp] = incl;
    __syncthreads();
    if (warp == 0 && lane < 8) {
        int b = shw[lane], ib = b;
        #pragma unroll
        for (int o = 1; o < 8; o <<= 1) {
            int t = __shfl_up_sync(0xffu, ib, o);
            if (lane >= o) ib += t;
        }
        shw[lane] = ib - b;
    }
    __syncthreads();
    if (tid < NBLK) d_bsum[y][tid] = shw[warp] + incl - val;
}

// ---------------- scan phase C: meta/cursors; re-zero counters ----------------
__global__ void k_scanC()
{
    int y = blockIdx.y;
    int lane = threadIdx.x & 31, warp = threadIdx.x >> 5;
    int base = blockIdx.x * CHUNK + threadIdx.x * ITEMS;

    int v[ITEMS]; int tsum = 0;
    #pragma unroll
    for (int j = 0; j < ITEMS; j++) {
        int i = base + j;
        v[j] = (i < N_NODES) ? d_cnt[y][i] : 0;
        tsum += v[j];
    }
    int incl = tsum;
    #pragma unroll
    for (int o = 1; o < 32; o <<= 1) {
        int t = __shfl_up_sync(0xffffffffu, incl, o);
        if (lane >= o) incl += t;
    }
    __shared__ int shw[8];
    if (lane == 31) shw[warp] = incl;
    __syncthreads();
    if (warp == 0 && lane < 8) {
        int b = shw[lane], ib = b;
        #pragma unroll
        for (int o = 1; o < 8; o <<= 1) {
            int t = __shfl_up_sync(0xffu, ib, o);
            if (lane >= o) ib += t;
        }
        shw[lane] = ib - b;
    }
    __syncthreads();
    int run = d_bsum[y][blockIdx.x] + shw[warp] + (incl - tsum);
    #pragma unroll
    for (int j = 0; j < ITEMS; j++) {
        int i = base + j;
        if (i < N_NODES) {
            int* mp = (int*)&d_meta[i];
            mp[y * 2 + 0] = run;          // base
            mp[y * 2 + 1] = v[j];         // degree
            d_cur[y][i]   = run;
            d_cnt[y][i]   = 0;            // self-clean for next call
            run += v[j];
        }
    }
}

// ---------------- fused CSR fill + feature init --------------------------------
__global__ void k_scatter_init(const int* __restrict__ src, const int* __restrict__ dst,
                               const int* __restrict__ nodes, const float* __restrict__ emb,
                               int E, int n)
{
    int idx = blockIdx.x * blockDim.x + threadIdx.x;
    if (idx < n * C) {
        int node = idx >> 5;
        int c    = idx & 31;
        int t    = __ldg(nodes + node);
        d_xh[0][idx] = __float2half_rn(__ldg(emb + t * C + c));
    }
    if (idx < E) {
        int s = __ldg(src + idx);
        int t = __ldg(dst + idx);
        int p = atomicAdd(&d_cur[0][t], 1);  d_csr[0][p] = s;
        int q = atomicAdd(&d_cur[1][s], 1);  d_csr[1][q] = t;
    }
}

// ---------------- mma.m16n8k16 helper -------------------------------------------
__device__ __forceinline__ void mma_16816(float* d,
                                          uint32_t a0, uint32_t a1, uint32_t a2, uint32_t a3,
                                          uint32_t b0, uint32_t b1)
{
    asm volatile(
        "mma.sync.aligned.m16n8k16.row.col.f32.f16.f16.f32 "
        "{%0,%1,%2,%3}, {%4,%5,%6,%7}, {%8,%9}, {%0,%1,%2,%3};"
        : "+f"(d[0]), "+f"(d[1]), "+f"(d[2]), "+f"(d[3])
        : "r"(a0), "r"(a1), "r"(a2), "r"(a3), "r"(b0), "r"(b1));
}

// ---------------- fused layer: staged CSR -> pipelined 8-wide gather -> mma ----
// 256 threads = 8 warps; 64 nodes/block. Fast path covers deg<=8 per direction
// (P(tail)~2%); node PAIRS are software-pipelined: all loads for 2 nodes issue
// before either node's accumulation, doubling loads in flight.
#define CAPI 512
__global__ void __launch_bounds__(256) k_layer(const __half* __restrict__ xin,
                                               __half* __restrict__ xout,
                                               const float* __restrict__ w, int n)
{
    __shared__ __half s_wt[2][32][32];   // 4 KB transposed weights
    __shared__ __half s_h [2][64][32];   // 8 KB aggregated features
    __shared__ __half s_x [64][32];      // 4 KB residual
    __shared__ int4   s_meta[64];        // 1 KB node meta
    __shared__ int    s_idx[2][CAPI];    // 4 KB CSR slices

    const int tid  = threadIdx.x;
    const int lane = tid & 31;
    const int warp = tid >> 5;
    const int cq   = lane & 7;            // channel quad (4 halves = 8 B)
    const int rs   = lane >> 3;           // row-in-batch 0..3
    const int blockBase = blockIdx.x * 64;
    const int lastLocal = min(64, n - blockBase);
    const unsigned FULL = 0xffffffffu;

    for (int i = tid; i < 2 * 32 * 32; i += 256) {
        int d = i >> 10, rem = i & 1023, k = rem >> 5, j = rem & 31;
        s_wt[d][j][k] = __float2half_rn(__ldg(w + d * 1024 + k * 32 + j));
    }
    if (tid < 64) {
        s_meta[tid] = (tid < lastLocal) ? __ldg(&d_meta[blockBase + tid])
                                        : make_int4(0, 0, 0, 0);
    }
    __syncthreads();

    const int4 mF = s_meta[0];
    const int4 mL = s_meta[lastLocal - 1];
    const int beg0 = mF.x, len0 = mL.x + mL.y - mF.x;
    const int beg1 = mF.z, len1 = mL.z + mL.w - mF.z;
    for (int i = tid; i < min(len0, CAPI); i += 256) s_idx[0][i] = __ldg(&d_csr[0][beg0 + i]);
    for (int i = tid; i < min(len1, CAPI); i += 256) s_idx[1][i] = __ldg(&d_csr[1][beg1 + i]);
    __syncthreads();

    // ---- gather: node pairs, stage-A loads then stage-B accumulate ----
    #pragma unroll
    for (int ni = 0; ni < 8; ni += 2) {
        int4  mA [2];
        uint2 xrA[2];
        uint2 w0a[2], w0b[2], w1a[2], w1b[2];

        // stage A: issue ALL loads for both nodes (independent)
        #pragma unroll
        for (int u = 0; u < 2; u++) {
            int nl = warp * 8 + ni + u;
            bool valid = nl < lastLocal;
            int4 m = valid ? s_meta[nl] : make_int4(beg0, 0, beg1, 0);
            mA[u] = m;
            uint2 z = make_uint2(0u, 0u);
            xrA[u] = valid ? __ldg((const uint2*)(xin + (size_t)(blockBase + nl) * C) + cq) : z;
            int o0 = m.x - beg0, o1 = m.z - beg1;
            w0a[u] = z; w0b[u] = z; w1a[u] = z; w1b[u] = z;
            if (rs < m.y) {
                int p = o0 + rs;
                int s = (p < CAPI) ? s_idx[0][p] : __ldg(&d_csr[0][beg0 + p]);
                w0a[u] = __ldg((const uint2*)(xin + (size_t)s * C) + cq);
            }
            if (rs + 4 < m.y) {
                int p = o0 + rs + 4;
                int s = (p < CAPI) ? s_idx[0][p] : __ldg(&d_csr[0][beg0 + p]);
                w0b[u] = __ldg((const uint2*)(xin + (size_t)s * C) + cq);
            }
            if (rs < m.w) {
                int p = o1 + rs;
                int s = (p < CAPI) ? s_idx[1][p] : __ldg(&d_csr[1][beg1 + p]);
                w1a[u] = __ldg((const uint2*)(xin + (size_t)s * C) + cq);
            }
            if (rs + 4 < m.w) {
                int p = o1 + rs + 4;
                int s = (p < CAPI) ? s_idx[1][p] : __ldg(&d_csr[1][beg1 + p]);
                w1b[u] = __ldg((const uint2*)(xin + (size_t)s * C) + cq);
            }
        }

        // stage B: accumulate, (rare) tail, reduce, store
        #pragma unroll
        for (int u = 0; u < 2; u++) {
            int nl = warp * 8 + ni + u;
            int4 m = mA[u];
            float2 xa = __half22float2(*(__half2*)&xrA[u].x);
            float2 xb = __half22float2(*(__half2*)&xrA[u].y);
            float f0, f1, f2, f3;
            if (rs == 0) { f0 = xa.x; f1 = xa.y; f2 = xb.x; f3 = xb.y; }
            else         { f0 = 0.f;  f1 = 0.f;  f2 = 0.f;  f3 = 0.f; }
            float g0 = f0, g1 = f1, g2 = f2, g3 = f3;

            float2 t0, t1;
            t0 = __half22float2(*(__half2*)&w0a[u].x);
            t1 = __half22float2(*(__half2*)&w0a[u].y);
            f0 += t0.x; f1 += t0.y; f2 += t1.x; f3 += t1.y;
            t0 = __half22float2(*(__half2*)&w0b[u].x);
            t1 = __half22float2(*(__half2*)&w0b[u].y);
            f0 += t0.x; f1 += t0.y; f2 += t1.x; f3 += t1.y;
            t0 = __half22float2(*(__half2*)&w1a[u].x);
            t1 = __half22float2(*(__half2*)&w1a[u].y);
            g0 += t0.x; g1 += t0.y; g2 += t1.x; g3 += t1.y;
            t0 = __half22float2(*(__half2*)&w1b[u].x);
            t1 = __half22float2(*(__half2*)&w1b[u].y);
            g0 += t0.x; g1 += t0.y; g2 += t1.x; g3 += t1.y;

            // rare tail (deg > 8)
            int p0 = m.y < 8 ? m.y : 8;
            int p1 = m.w < 8 ? m.w : 8;
            if (p0 < m.y || p1 < m.w) {
                int o0 = m.x - beg0, o1 = m.z - beg1;
                while (p0 < m.y || p1 < m.w) {
                    int n0 = m.y - p0; if (n0 < 0) n0 = 0; if (n0 > 4) n0 = 4;
                    int n1 = m.w - p1; if (n1 < 0) n1 = 0; if (n1 > 4) n1 = 4;
                    uint2 v0 = make_uint2(0u, 0u), v1 = make_uint2(0u, 0u);
                    if (rs < n0) {
                        int p = o0 + p0 + rs;
                        int s = (p < CAPI) ? s_idx[0][p] : __ldg(&d_csr[0][beg0 + p]);
                        v0 = __ldg((const uint2*)(xin + (size_t)s * C) + cq);
                    }
                    if (rs < n1) {
                        int p = o1 + p1 + rs;
                        int s = (p < CAPI) ? s_idx[1][p] : __ldg(&d_csr[1][beg1 + p]);
                        v1 = __ldg((const uint2*)(xin + (size_t)s * C) + cq);
                    }
                    t0 = __half22float2(*(__half2*)&v0.x);
                    t1 = __half22float2(*(__half2*)&v0.y);
                    f0 += t0.x; f1 += t0.y; f2 += t1.x; f3 += t1.y;
                    t0 = __half22float2(*(__half2*)&v1.x);
                    t1 = __half22float2(*(__half2*)&v1.y);
                    g0 += t0.x; g1 += t0.y; g2 += t1.x; g3 += t1.y;
                    p0 += n0; p1 += n1;
                }
            }

            // reduce over the 4 row-groups
            f0 += __shfl_xor_sync(FULL, f0, 8);  f0 += __shfl_xor_sync(FULL, f0, 16);
            f1 += __shfl_xor_sync(FULL, f1, 8);  f1 += __shfl_xor_sync(FULL, f1, 16);
            f2 += __shfl_xor_sync(FULL, f2, 8);  f2 += __shfl_xor_sync(FULL, f2, 16);
            f3 += __shfl_xor_sync(FULL, f3, 8);  f3 += __shfl_xor_sync(FULL, f3, 16);
            g0 += __shfl_xor_sync(FULL, g0, 8);  g0 += __shfl_xor_sync(FULL, g0, 16);
            g1 += __shfl_xor_sync(FULL, g1, 8);  g1 += __shfl_xor_sync(FULL, g1, 16);
            g2 += __shfl_xor_sync(FULL, g2, 8);  g2 += __shfl_xor_sync(FULL, g2, 16);
            g3 += __shfl_xor_sync(FULL, g3, 8);  g3 += __shfl_xor_sync(FULL, g3, 16);

            float nf = __fdividef(1.f, 1.f + (float)m.y);
            float nb = __fdividef(1.f, 1.f + (float)m.w);

            if (rs == 0) {
                __half2 hf0 = __floats2half2_rn(f0 * nf, f1 * nf);
                __half2 hf1 = __floats2half2_rn(f2 * nf, f3 * nf);
                __half2 hb0 = __floats2half2_rn(g0 * nb, g1 * nb);
                __half2 hb1 = __floats2half2_rn(g2 * nb, g3 * nb);
                uint2 pf; pf.x = *(uint32_t*)&hf0; pf.y = *(uint32_t*)&hf1;
                uint2 pb; pb.x = *(uint32_t*)&hb0; pb.y = *(uint32_t*)&hb1;
                *(uint2*)&s_h[0][nl][cq * 4] = pf;
                *(uint2*)&s_h[1][nl][cq * 4] = pb;
                *(uint2*)&s_x[nl][cq * 4]    = xrA[u];
            }
        }
    }
    __syncthreads();

    // ---- GEMM + epilogue: warps 0..3, warp = m-tile (16 nodes), both dirs ----
    if (warp < 4) {
        const int g  = lane >> 2;
        const int t  = lane & 3;
        const int m0 = warp * 16;

        float acc0[4][4], acc1[4][4];
        #pragma unroll
        for (int nt = 0; nt < 4; nt++)
            #pragma unroll
            for (int i = 0; i < 4; i++) { acc0[nt][i] = 0.f; acc1[nt][i] = 0.f; }

        #pragma unroll
        for (int kt = 0; kt < 32; kt += 16) {
            uint32_t a0 = *(const uint32_t*)&s_h[0][m0 + g    ][kt + t * 2];
            uint32_t a1 = *(const uint32_t*)&s_h[0][m0 + g + 8][kt + t * 2];
            uint32_t a2 = *(const uint32_t*)&s_h[0][m0 + g    ][kt + t * 2 + 8];
            uint32_t a3 = *(const uint32_t*)&s_h[0][m0 + g + 8][kt + t * 2 + 8];
            #pragma unroll
            for (int nt = 0; nt < 4; nt++) {
                uint32_t b0 = *(const uint32_t*)&s_wt[0][nt * 8 + g][kt + t * 2];
                uint32_t b1 = *(const uint32_t*)&s_wt[0][nt * 8 + g][kt + t * 2 + 8];
                mma_16816(acc0[nt], a0, a1, a2, a3, b0, b1);
            }
            a0 = *(const uint32_t*)&s_h[1][m0 + g    ][kt + t * 2];
            a1 = *(const uint32_t*)&s_h[1][m0 + g + 8][kt + t * 2];
            a2 = *(const uint32_t*)&s_h[1][m0 + g    ][kt + t * 2 + 8];
            a3 = *(const uint32_t*)&s_h[1][m0 + g + 8][kt + t * 2 + 8];
            #pragma unroll
            for (int nt = 0; nt < 4; nt++) {
                uint32_t b0 = *(const uint32_t*)&s_wt[1][nt * 8 + g][kt + t * 2];
                uint32_t b1 = *(const uint32_t*)&s_wt[1][nt * 8 + g][kt + t * 2 + 8];
                mma_16816(acc1[nt], a0, a1, a2, a3, b0, b1);
            }
        }

        int node0 = blockBase + m0 + g;
        int node1 = node0 + 8;
        #pragma unroll
        for (int nt = 0; nt < 4; nt++) {
            int col = nt * 8 + t * 2;
            float2 xv0 = __half22float2(*(__half2*)&s_x[m0 + g    ][col]);
            float2 xv1 = __half22float2(*(__half2*)&s_x[m0 + g + 8][col]);
            float o00 = xv0.x + fmaxf(acc0[nt][0], 0.f) + fmaxf(acc1[nt][0], 0.f);
            float o01 = xv0.y + fmaxf(acc0[nt][1], 0.f) + fmaxf(acc1[nt][1], 0.f);
            float o10 = xv1.x + fmaxf(acc0[nt][2], 0.f) + fmaxf(acc1[nt][2], 0.f);
            float o11 = xv1.y + fmaxf(acc0[nt][3], 0.f) + fmaxf(acc1[nt][3], 0.f);
            if (node0 < n)
                *(__half2*)&xout[(size_t)node0 * C + col] = __floats2half2_rn(o00, o01);
            if (node1 < n)
                *(__half2*)&xout[(size_t)node1 * C + col] = __floats2half2_rn(o10, o11);
        }
    }
}

// ---------------- pooling: per-graph sum + count (batch sorted) ----------------
__global__ void k_pool(const int* __restrict__ batch, const __half* __restrict__ x, int n)
{
    int lane = threadIdx.x & 31;
    int warp = threadIdx.x >> 5;
    int base = blockIdx.x * 256 + warp * 32;

    float acc = 0.f;
    int cur = -1, run = 0;
    for (int j = 0; j < 32; j++) {
        int node = base + j;
        if (node >= n) break;
        int b = __ldg(batch + node);
        float v = __half2float(__ldg(x + (size_t)node * C + lane));
        if (b != cur) {
            if (cur >= 0) {
                atomicAdd(&d_gsum[cur * C + lane], acc);
                if (lane == 0) atomicAdd(&d_gcnt[cur], (float)run);
            }
            cur = b; acc = 0.f; run = 0;
        }
        acc += v; run++;
    }
    if (cur >= 0) {
        atomicAdd(&d_gsum[cur * C + lane], acc);
        if (lane == 0) atomicAdd(&d_gcnt[cur], (float)run);
    }
}

// ---------------- MLP head: 8 graphs per block; self-cleans pool buffers -------
#define GPB 8
__global__ void k_mlp(const float* __restrict__ hw, const float* __restrict__ hb,
                      const float* __restrict__ ow, float* __restrict__ out)
{
    __shared__ float gs[GPB][C];
    __shared__ float sout[GPB];
    int tid = threadIdx.x;
    if (tid < GPB * C) {
        int g = tid >> 5, c = tid & 31;
        int gb = blockIdx.x * GPB + g;
        gs[g][c] = d_gsum[gb * C + c] / d_gcnt[gb];
    }
    if (tid < GPB) sout[tid] = 0.f;
    __syncthreads();
    if (tid < GPB * C) {
        int g = tid >> 5, c = tid & 31;
        d_gsum[(blockIdx.x * GPB + g) * C + c] = 0.f;
    }
    if (tid < GPB) d_gcnt[blockIdx.x * GPB + tid] = 0.f;

    float part[GPB];
    #pragma unroll
    for (int g = 0; g < GPB; g++) part[g] = 0.f;

    for (int j = tid; j < HIDDEN; j += 256) {
        float h[GPB];
        float bj = __ldg(hb + j);
        #pragma unroll
        for (int g = 0; g < GPB; g++) h[g] = bj;
        #pragma unroll
        for (int k = 0; k < C; k++) {
            float wkj = __ldg(hw + k * HIDDEN + j);
            #pragma unroll
            for (int g = 0; g < GPB; g++)
                h[g] = fmaf(gs[g][k], wkj, h[g]);
        }
        float oj = __ldg(ow + j);
        #pragma unroll
        for (int g = 0; g < GPB; g++)
            part[g] += fmaxf(h[g], 0.f) * oj;
    }
    #pragma unroll
    for (int g = 0; g < GPB; g++) {
        float v = part[g];
        #pragma unroll
        for (int off = 16; off > 0; off >>= 1)
            v += __shfl_down_sync(0xffffffffu, v, off);
        if ((tid & 31) == 0) atomicAdd(&sout[g], v);
    }
    __syncthreads();
    if (tid < GPB) out[blockIdx.x * GPB + tid] = sout[tid];
}

// ---------------- launch ---------------------------------------------------------
extern "C" void kernel_launch(void* const* d_in, const int* in_sizes, int n_in,
                              void* d_out, int out_size)
{
    const int*   nodes    = (const int*)  d_in[0];
    const int*   sources  = (const int*)  d_in[1];
    const int*   targets  = (const int*)  d_in[2];
    const int*   batch    = (const int*)  d_in[3];
    const float* emb      = (const float*)d_in[4];
    const float* conv_w   = (const float*)d_in[5];
    const float* hidden_w = (const float*)d_in[6];
    const float* hidden_b = (const float*)d_in[7];
    const float* out_w    = (const float*)d_in[8];
    float*       out      = (float*)d_out;

    const int N = in_sizes[0];
    const int E = in_sizes[1];

    // CSR build
    k_hist        <<<(E + 255) / 256, 256>>>(sources, targets, E);
    k_scanA       <<<dim3(NBLK, 2), SCAN_BLK>>>();
    k_scanB       <<<dim3(1, 2),    SCAN_BLK>>>();
    k_scanC       <<<dim3(NBLK, 2), SCAN_BLK>>>();
    k_scatter_init<<<(N * C + 255) / 256, 256>>>(sources, targets, nodes, emb, E, N);

    // 8 fused layers, ping-pong (even count -> final in buffer 0)
    const int nb = (N + 63) / 64;
    __half* xh = nullptr;
    cudaGetSymbolAddress((void**)&xh, d_xh);
    __half* xa = xh;
    __half* xb = xh + (size_t)N_NODES * C;
    for (int l = 0; l < LAYERS; l++) {
        const float* wl = conv_w + (size_t)l * 2 * C * C;
        if ((l & 1) == 0) k_layer<<<nb, 256>>>(xa, xb, wl, N);
        else              k_layer<<<nb, 256>>>(xb, xa, wl, N);
    }
    k_pool<<<(N + 255) / 256, 256>>>(batch, xa, N);

    k_mlp<<<NGRAPH / GPB, 256>>>(hidden_w, hidden_b, out_w, out);
}